// round 8
// baseline (speedup 1.0000x reference)
#include <cuda_runtime.h>
#include <cuda_fp16.h>
#include <cstdint>

#define N_NODES 100000
#define N_EDGES 3200000
#define D_FEAT  128
#define HIDDEN  16
#define NCLS    7
#define H2PAD   8
#define NB_SCAN ((N_NODES + 1023) / 1024)   // 98 scan blocks

// ---- scratch (static __device__ arrays; no allocation allowed) ----
__device__ int    d_cd  [2 * N_NODES];        // interleaved {count, deg_as_float}
__device__ float  d_dinv[N_NODES];
__device__ __half d_g1h [N_NODES * HIDDEN];   // fp16 messages, layer 1
__device__ __half d_g2h [N_NODES * H2PAD];    // fp16 messages, layer 2
__device__ int    d_off   [N_NODES + 1];
__device__ int    d_cursor[N_NODES];
__device__ int    d_btot  [NB_SCAN];
__device__ int2   d_edge_s[N_EDGES];          // dst-sorted {src, w_as_int}

// ---------------- init ----------------
__global__ void k_zero() {
    int n = blockIdx.x * blockDim.x + threadIdx.x;
    if (n < N_NODES) {
        d_cd[2 * n]     = 0;
        d_cd[2 * n + 1] = __float_as_int(1.0f);   // self-loop weight
    }
}

// histogram + weighted degree, both atomics on the same 8B pair
__global__ void k_hist(const int* __restrict__ ei,
                       const float* __restrict__ ew) {
    int e = blockIdx.x * blockDim.x + threadIdx.x;
    if (e >= N_EDGES) return;
    int dst = ei[N_EDGES + e];
    atomicAdd(&d_cd[2 * dst], 1);
    atomicAdd((float*)&d_cd[2 * dst + 1], ew[e]);
}

__global__ void __launch_bounds__(1024) k_scanA() {
    __shared__ int s[1024];
    int tid = threadIdx.x;
    int i = blockIdx.x * 1024 + tid;
    int v = (i < N_NODES) ? d_cd[2 * i] : 0;
    s[tid] = v;
    __syncthreads();
#pragma unroll
    for (int off = 1; off < 1024; off <<= 1) {
        int t = (tid >= off) ? s[tid - off] : 0;
        __syncthreads();
        s[tid] += t;
        __syncthreads();
    }
    if (i < N_NODES) d_off[i] = s[tid] - v;       // exclusive within block
    if (tid == 1023) d_btot[blockIdx.x] = s[1023];
}

// scanC with the 98-element block-total scan done per-block in smem
__global__ void __launch_bounds__(256) k_scanC() {
    __shared__ int sin[128], sscan[128];
    int t = threadIdx.x;
    if (t < 128) {
        int v = (t < NB_SCAN) ? d_btot[t] : 0;
        sin[t] = v;
        sscan[t] = v;
    }
    __syncthreads();
#pragma unroll
    for (int off = 1; off < 128; off <<= 1) {
        int tmp = (t >= off && t < 128) ? sscan[t - off] : 0;
        __syncthreads();
        if (t < 128) sscan[t] += tmp;
        __syncthreads();
    }
    int i = blockIdx.x * blockDim.x + t;
    if (i < N_NODES) {
        int k = i >> 10;
        int o = d_off[i] + (sscan[k] - sin[k]);   // + exclusive block offset
        d_off[i] = o;
        d_cursor[i] = o;
    }
    if (i == 0) d_off[N_NODES] = N_EDGES;
}

__global__ void k_reorder(const int* __restrict__ ei,
                          const float* __restrict__ ew) {
    int e = blockIdx.x * blockDim.x + threadIdx.x;
    if (e >= N_EDGES) return;
    int src = ei[e];
    int dst = ei[N_EDGES + e];
    int pos = atomicAdd(&d_cursor[dst], 1);
    d_edge_s[pos] = make_int2(src, __float_as_int(ew[e]));
}

// ---------------- layer 1 projection: g1h = half((x @ W1) * dinv) ----------------
#define KCHUNK 16
__global__ void __launch_bounds__(256) k_gemm1(const float* __restrict__ x,
                                               const float* __restrict__ W1) {
    __shared__ float sW[D_FEAT * HIDDEN];
    __shared__ float sx[256][KCHUNK + 1];
    for (int i = threadIdx.x; i < D_FEAT * HIDDEN; i += blockDim.x)
        sW[i] = W1[i];

    int tid = threadIdx.x;
    int n0 = blockIdx.x * 256;
    int n  = n0 + tid;
    int nrows = min(256, N_NODES - n0);

    float acc[HIDDEN];
#pragma unroll
    for (int j = 0; j < HIDDEN; j++) acc[j] = 0.0f;

    for (int c = 0; c < D_FEAT / KCHUNK; c++) {
        __syncthreads();
        int nvec = nrows * (KCHUNK / 4);
        for (int idx = tid; idx < nvec; idx += 256) {
            int r = idx >> 2;
            int q = idx & 3;
            float4 v = *(const float4*)(x + (size_t)(n0 + r) * D_FEAT + c * KCHUNK + q * 4);
            sx[r][q * 4 + 0] = v.x;
            sx[r][q * 4 + 1] = v.y;
            sx[r][q * 4 + 2] = v.z;
            sx[r][q * 4 + 3] = v.w;
        }
        __syncthreads();
        if (n < N_NODES) {
#pragma unroll
            for (int kk = 0; kk < KCHUNK; kk++) {
                float v = sx[tid][kk];
                const float* wrow = &sW[(c * KCHUNK + kk) * HIDDEN];
#pragma unroll
                for (int j = 0; j < HIDDEN; j++)
                    acc[j] = fmaf(v, wrow[j], acc[j]);
            }
        }
    }

    if (n >= N_NODES) return;
    float di = rsqrtf(__int_as_float(d_cd[2 * n + 1]));
    d_dinv[n] = di;
    half2* g = (half2*)(d_g1h + (size_t)n * HIDDEN);
#pragma unroll
    for (int p = 0; p < HIDDEN / 2; p++)
        g[p] = __floats2half2_rn(acc[2*p] * di, acc[2*p+1] * di);
}

// ---- fused: aggregate layer 1 + relu/bias + W2 projection -> g2h ----
__global__ void k_agg1l2(const float* __restrict__ b1,
                         const float* __restrict__ W2) {
    int wg = (blockIdx.x * blockDim.x + threadIdx.x) >> 5;
    int lane = threadIdx.x & 31;
    if (wg >= N_NODES) return;
    int start = d_off[wg], end = d_off[wg + 1];
    int q = lane & 3;       // which 4-half chunk of the 16-half row
    int j = lane >> 2;      // edge slot 0..7
    float4 acc = make_float4(0.f, 0.f, 0.f, 0.f);
    for (int i = start + j; i < end; i += 8) {
        int2 ed = d_edge_s[i];
        float w = __int_as_float(ed.y);
        uint2 pk = *(const uint2*)(d_g1h + (size_t)ed.x * HIDDEN + q * 4);
        float2 lo = __half22float2(*(const half2*)&pk.x);
        float2 hi = __half22float2(*(const half2*)&pk.y);
        acc.x = fmaf(lo.x, w, acc.x);
        acc.y = fmaf(lo.y, w, acc.y);
        acc.z = fmaf(hi.x, w, acc.z);
        acc.w = fmaf(hi.y, w, acc.w);
    }
#pragma unroll
    for (int off = 16; off >= 4; off >>= 1) {
        acc.x += __shfl_down_sync(0xffffffff, acc.x, off);
        acc.y += __shfl_down_sync(0xffffffff, acc.y, off);
        acc.z += __shfl_down_sync(0xffffffff, acc.z, off);
        acc.w += __shfl_down_sync(0xffffffff, acc.w, off);
    }
    // lanes 0..3 now hold the aggregated row chunk q = lane
    float di = d_dinv[wg];
    {
        uint2 pk = *(const uint2*)(d_g1h + (size_t)wg * HIDDEN + q * 4);
        float2 lo = __half22float2(*(const half2*)&pk.x);
        float2 hi = __half22float2(*(const half2*)&pk.y);
        acc.x += lo.x; acc.y += lo.y; acc.z += hi.x; acc.w += hi.y;  // self loop
    }
    // h chunk: relu(acc*di + b1)
    float h0 = fmaxf(acc.x * di + __ldg(&b1[q * 4 + 0]), 0.0f);
    float h1 = fmaxf(acc.y * di + __ldg(&b1[q * 4 + 1]), 0.0f);
    float h2 = fmaxf(acc.z * di + __ldg(&b1[q * 4 + 2]), 0.0f);
    float h3 = fmaxf(acc.w * di + __ldg(&b1[q * 4 + 3]), 0.0f);
    // partial o over this lane's 4 hidden dims
    float o[NCLS];
#pragma unroll
    for (int c = 0; c < NCLS; c++) {
        o[c] = h0 * __ldg(&W2[(q * 4 + 0) * NCLS + c])
             + h1 * __ldg(&W2[(q * 4 + 1) * NCLS + c])
             + h2 * __ldg(&W2[(q * 4 + 2) * NCLS + c])
             + h3 * __ldg(&W2[(q * 4 + 3) * NCLS + c]);
    }
    // reduce partial o across lanes 0..3
#pragma unroll
    for (int c = 0; c < NCLS; c++) {
        o[c] += __shfl_xor_sync(0xffffffff, o[c], 1);
        o[c] += __shfl_xor_sync(0xffffffff, o[c], 2);
    }
    if (lane == 0) {
        half2* g = (half2*)(d_g2h + (size_t)wg * H2PAD);
        g[0] = __floats2half2_rn(o[0] * di, o[1] * di);
        g[1] = __floats2half2_rn(o[2] * di, o[3] * di);
        g[2] = __floats2half2_rn(o[4] * di, o[5] * di);
        g[3] = __floats2half2_rn(o[6] * di, 0.0f);
    }
}

// ---- fused: aggregate layer 2 + log_softmax -> out ----
__global__ void k_agg2out(const float* __restrict__ b2,
                          float* __restrict__ out) {
    int wg = (blockIdx.x * blockDim.x + threadIdx.x) >> 5;
    int lane = threadIdx.x & 31;
    if (wg >= N_NODES) return;
    int start = d_off[wg], end = d_off[wg + 1];
    int q = lane & 1;       // which 4-half chunk of the 8-half row
    int j = lane >> 1;      // edge slot 0..15
    float4 acc = make_float4(0.f, 0.f, 0.f, 0.f);
    for (int i = start + j; i < end; i += 16) {
        int2 ed = d_edge_s[i];
        float w = __int_as_float(ed.y);
        uint2 pk = *(const uint2*)(d_g2h + (size_t)ed.x * H2PAD + q * 4);
        float2 lo = __half22float2(*(const half2*)&pk.x);
        float2 hi = __half22float2(*(const half2*)&pk.y);
        acc.x = fmaf(lo.x, w, acc.x);
        acc.y = fmaf(lo.y, w, acc.y);
        acc.z = fmaf(hi.x, w, acc.z);
        acc.w = fmaf(hi.y, w, acc.w);
    }
#pragma unroll
    for (int off = 16; off >= 2; off >>= 1) {
        acc.x += __shfl_down_sync(0xffffffff, acc.x, off);
        acc.y += __shfl_down_sync(0xffffffff, acc.y, off);
        acc.z += __shfl_down_sync(0xffffffff, acc.z, off);
        acc.w += __shfl_down_sync(0xffffffff, acc.w, off);
    }
    // lanes 0,1 hold chunks 0,1; add self loop
    {
        uint2 pk = *(const uint2*)(d_g2h + (size_t)wg * H2PAD + q * 4);
        float2 lo = __half22float2(*(const half2*)&pk.x);
        float2 hi = __half22float2(*(const half2*)&pk.y);
        acc.x += lo.x; acc.y += lo.y; acc.z += hi.x; acc.w += hi.y;
    }
    // lane 0 collects lane 1's chunk
    float4 other;
    other.x = __shfl_down_sync(0xffffffff, acc.x, 1);
    other.y = __shfl_down_sync(0xffffffff, acc.y, 1);
    other.z = __shfl_down_sync(0xffffffff, acc.z, 1);
    other.w = __shfl_down_sync(0xffffffff, acc.w, 1);
    if (lane == 0) {
        float di = d_dinv[wg];
        float v[NCLS];
        v[0] = acc.x   * di + __ldg(&b2[0]);
        v[1] = acc.y   * di + __ldg(&b2[1]);
        v[2] = acc.z   * di + __ldg(&b2[2]);
        v[3] = acc.w   * di + __ldg(&b2[3]);
        v[4] = other.x * di + __ldg(&b2[4]);
        v[5] = other.y * di + __ldg(&b2[5]);
        v[6] = other.z * di + __ldg(&b2[6]);
        float m = v[0];
#pragma unroll
        for (int c = 1; c < NCLS; c++) m = fmaxf(m, v[c]);
        float s = 0.0f;
#pragma unroll
        for (int c = 0; c < NCLS; c++) s += expf(v[c] - m);
        float lse = m + logf(s);
#pragma unroll
        for (int c = 0; c < NCLS; c++)
            out[(size_t)wg * NCLS + c] = v[c] - lse;
    }
}

extern "C" void kernel_launch(void* const* d_in, const int* in_sizes, int n_in,
                              void* d_out, int out_size) {
    const float* x  = (const float*)d_in[0];
    const int*   ei = (const int*)d_in[1];
    const float* ew = (const float*)d_in[2];
    const float* W1 = (const float*)d_in[3];
    const float* b1 = (const float*)d_in[4];
    const float* W2 = (const float*)d_in[5];
    const float* b2 = (const float*)d_in[6];
    float* out = (float*)d_out;

    const int TB = 256;
    const int nodeGrid = (N_NODES + TB - 1) / TB;
    const int edgeGrid = (N_EDGES + TB - 1) / TB;
    const int warpNodeGrid = (N_NODES * 32 + TB - 1) / TB;   // warp per node

    k_zero<<<nodeGrid, TB>>>();
    k_hist<<<edgeGrid, TB>>>(ei, ew);
    k_scanA<<<NB_SCAN, 1024>>>();
    k_scanC<<<nodeGrid, TB>>>();
    k_reorder<<<edgeGrid, TB>>>(ei, ew);
    k_gemm1<<<nodeGrid, TB>>>(x, W1);
    k_agg1l2<<<warpNodeGrid, TB>>>(b1, W2);
    k_agg2out<<<warpNodeGrid, TB>>>(b2, out);
}

// round 9
// speedup vs baseline: 1.0440x; 1.0440x over previous
#include <cuda_runtime.h>
#include <cuda_fp16.h>
#include <cstdint>

#define N_NODES 100000
#define N_EDGES 3200000
#define D_FEAT  128
#define HIDDEN  16
#define NCLS    7
#define H2PAD   8
#define NB_SCAN ((N_NODES + 1023) / 1024)   // 98 scan blocks

// ---- scratch (static __device__ arrays; no allocation allowed) ----
__device__ int    d_cd  [2 * N_NODES];        // interleaved {count, deg_as_float}
__device__ float  d_dinv[N_NODES];
__device__ __half d_g1h [N_NODES * HIDDEN];   // fp16 messages, layer 1
__device__ __half d_g2h [N_NODES * H2PAD];    // fp16 messages, layer 2
__device__ int    d_off   [N_NODES + 1];
__device__ int    d_cursor[N_NODES];
__device__ int    d_btot  [NB_SCAN];
__device__ int2   d_edge_s[N_EDGES];          // dst-sorted {src, w_as_int}

// ---------------- init ----------------
__global__ void k_zero() {
    int n = blockIdx.x * blockDim.x + threadIdx.x;
    if (n < N_NODES) {
        d_cd[2 * n]     = 0;
        d_cd[2 * n + 1] = __float_as_int(1.0f);   // self-loop weight
    }
}

// histogram + weighted degree
__global__ void k_hist(const int* __restrict__ ei,
                       const float* __restrict__ ew) {
    int e = blockIdx.x * blockDim.x + threadIdx.x;
    if (e >= N_EDGES) return;
    int dst = ei[N_EDGES + e];
    atomicAdd(&d_cd[2 * dst], 1);
    atomicAdd((float*)&d_cd[2 * dst + 1], ew[e]);
}

__global__ void __launch_bounds__(1024) k_scanA() {
    __shared__ int s[1024];
    int tid = threadIdx.x;
    int i = blockIdx.x * 1024 + tid;
    int v = (i < N_NODES) ? d_cd[2 * i] : 0;
    s[tid] = v;
    __syncthreads();
#pragma unroll
    for (int off = 1; off < 1024; off <<= 1) {
        int t = (tid >= off) ? s[tid - off] : 0;
        __syncthreads();
        s[tid] += t;
        __syncthreads();
    }
    if (i < N_NODES) d_off[i] = s[tid] - v;       // exclusive within block
    if (tid == 1023) d_btot[blockIdx.x] = s[1023];
}

// scanC with the 98-element block-total scan done per-block in smem
__global__ void __launch_bounds__(256) k_scanC() {
    __shared__ int sin[128], sscan[128];
    int t = threadIdx.x;
    if (t < 128) {
        int v = (t < NB_SCAN) ? d_btot[t] : 0;
        sin[t] = v;
        sscan[t] = v;
    }
    __syncthreads();
#pragma unroll
    for (int off = 1; off < 128; off <<= 1) {
        int tmp = (t >= off && t < 128) ? sscan[t - off] : 0;
        __syncthreads();
        if (t < 128) sscan[t] += tmp;
        __syncthreads();
    }
    int i = blockIdx.x * blockDim.x + t;
    if (i < N_NODES) {
        int k = i >> 10;
        int o = d_off[i] + (sscan[k] - sin[k]);   // + exclusive block offset
        d_off[i] = o;
        d_cursor[i] = o;
    }
    if (i == 0) d_off[N_NODES] = N_EDGES;
}

__global__ void k_reorder(const int* __restrict__ ei,
                          const float* __restrict__ ew) {
    int e = blockIdx.x * blockDim.x + threadIdx.x;
    if (e >= N_EDGES) return;
    int src = ei[e];
    int dst = ei[N_EDGES + e];
    int pos = atomicAdd(&d_cursor[dst], 1);
    d_edge_s[pos] = make_int2(src, __float_as_int(ew[e]));
}

// ---------------- layer 1 projection: g1h = half((x @ W1) * dinv) ----------------
#define KCHUNK 16
__global__ void __launch_bounds__(256) k_gemm1(const float* __restrict__ x,
                                               const float* __restrict__ W1) {
    __shared__ float sW[D_FEAT * HIDDEN];
    __shared__ float sx[256][KCHUNK + 1];
    for (int i = threadIdx.x; i < D_FEAT * HIDDEN; i += blockDim.x)
        sW[i] = W1[i];

    int tid = threadIdx.x;
    int n0 = blockIdx.x * 256;
    int n  = n0 + tid;
    int nrows = min(256, N_NODES - n0);

    float acc[HIDDEN];
#pragma unroll
    for (int j = 0; j < HIDDEN; j++) acc[j] = 0.0f;

    for (int c = 0; c < D_FEAT / KCHUNK; c++) {
        __syncthreads();
        int nvec = nrows * (KCHUNK / 4);
        for (int idx = tid; idx < nvec; idx += 256) {
            int r = idx >> 2;
            int q = idx & 3;
            float4 v = *(const float4*)(x + (size_t)(n0 + r) * D_FEAT + c * KCHUNK + q * 4);
            sx[r][q * 4 + 0] = v.x;
            sx[r][q * 4 + 1] = v.y;
            sx[r][q * 4 + 2] = v.z;
            sx[r][q * 4 + 3] = v.w;
        }
        __syncthreads();
        if (n < N_NODES) {
#pragma unroll
            for (int kk = 0; kk < KCHUNK; kk++) {
                float v = sx[tid][kk];
                const float* wrow = &sW[(c * KCHUNK + kk) * HIDDEN];
#pragma unroll
                for (int j = 0; j < HIDDEN; j++)
                    acc[j] = fmaf(v, wrow[j], acc[j]);
            }
        }
    }

    if (n >= N_NODES) return;
    float di = rsqrtf(__int_as_float(d_cd[2 * n + 1]));
    d_dinv[n] = di;
    half2* g = (half2*)(d_g1h + (size_t)n * HIDDEN);
#pragma unroll
    for (int p = 0; p < HIDDEN / 2; p++)
        g[p] = __floats2half2_rn(acc[2*p] * di, acc[2*p+1] * di);
}

// ---- fused: aggregate layer 1 + relu/bias + W2 projection -> g2h ----
// Epilogue predicated to lanes 0..3 (the lanes holding the reduced row).
__global__ void k_agg1l2(const float* __restrict__ b1,
                         const float* __restrict__ W2) {
    int wg = (blockIdx.x * blockDim.x + threadIdx.x) >> 5;
    int lane = threadIdx.x & 31;
    if (wg >= N_NODES) return;
    int start = d_off[wg], end = d_off[wg + 1];
    int q = lane & 3;       // which 4-half chunk of the 16-half row
    int j = lane >> 2;      // edge slot 0..7
    float4 acc = make_float4(0.f, 0.f, 0.f, 0.f);
    for (int i = start + j; i < end; i += 8) {
        int2 ed = d_edge_s[i];
        float w = __int_as_float(ed.y);
        uint2 pk = *(const uint2*)(d_g1h + (size_t)ed.x * HIDDEN + q * 4);
        float2 lo = __half22float2(*(const half2*)&pk.x);
        float2 hi = __half22float2(*(const half2*)&pk.y);
        acc.x = fmaf(lo.x, w, acc.x);
        acc.y = fmaf(lo.y, w, acc.y);
        acc.z = fmaf(hi.x, w, acc.z);
        acc.w = fmaf(hi.y, w, acc.w);
    }
#pragma unroll
    for (int off = 16; off >= 4; off >>= 1) {
        acc.x += __shfl_down_sync(0xffffffff, acc.x, off);
        acc.y += __shfl_down_sync(0xffffffff, acc.y, off);
        acc.z += __shfl_down_sync(0xffffffff, acc.z, off);
        acc.w += __shfl_down_sync(0xffffffff, acc.w, off);
    }
    if (lane < 4) {
        float di = d_dinv[wg];
        uint2 pk = *(const uint2*)(d_g1h + (size_t)wg * HIDDEN + q * 4);
        float2 lo = __half22float2(*(const half2*)&pk.x);
        float2 hi = __half22float2(*(const half2*)&pk.y);
        acc.x += lo.x; acc.y += lo.y; acc.z += hi.x; acc.w += hi.y;  // self loop
        // h chunk: relu(acc*di + b1)
        float h0 = fmaxf(acc.x * di + __ldg(&b1[q * 4 + 0]), 0.0f);
        float h1 = fmaxf(acc.y * di + __ldg(&b1[q * 4 + 1]), 0.0f);
        float h2 = fmaxf(acc.z * di + __ldg(&b1[q * 4 + 2]), 0.0f);
        float h3 = fmaxf(acc.w * di + __ldg(&b1[q * 4 + 3]), 0.0f);
        // partial o over this lane's 4 hidden dims
        float o[NCLS];
#pragma unroll
        for (int c = 0; c < NCLS; c++) {
            o[c] = h0 * __ldg(&W2[(q * 4 + 0) * NCLS + c])
                 + h1 * __ldg(&W2[(q * 4 + 1) * NCLS + c])
                 + h2 * __ldg(&W2[(q * 4 + 2) * NCLS + c])
                 + h3 * __ldg(&W2[(q * 4 + 3) * NCLS + c]);
        }
        // reduce partial o across lanes 0..3 (sub-warp, mask 0xF)
#pragma unroll
        for (int c = 0; c < NCLS; c++) {
            o[c] += __shfl_xor_sync(0xF, o[c], 1);
            o[c] += __shfl_xor_sync(0xF, o[c], 2);
        }
        if (lane == 0) {
            half2* g = (half2*)(d_g2h + (size_t)wg * H2PAD);
            g[0] = __floats2half2_rn(o[0] * di, o[1] * di);
            g[1] = __floats2half2_rn(o[2] * di, o[3] * di);
            g[2] = __floats2half2_rn(o[4] * di, o[5] * di);
            g[3] = __floats2half2_rn(o[6] * di, 0.0f);
        }
    }
}

// ---- fused: aggregate layer 2 + log_softmax -> out ----
// Epilogue predicated to lanes 0..1.
__global__ void k_agg2out(const float* __restrict__ b2,
                          float* __restrict__ out) {
    int wg = (blockIdx.x * blockDim.x + threadIdx.x) >> 5;
    int lane = threadIdx.x & 31;
    if (wg >= N_NODES) return;
    int start = d_off[wg], end = d_off[wg + 1];
    int q = lane & 1;       // which 4-half chunk of the 8-half row
    int j = lane >> 1;      // edge slot 0..15
    float4 acc = make_float4(0.f, 0.f, 0.f, 0.f);
    for (int i = start + j; i < end; i += 16) {
        int2 ed = d_edge_s[i];
        float w = __int_as_float(ed.y);
        uint2 pk = *(const uint2*)(d_g2h + (size_t)ed.x * H2PAD + q * 4);
        float2 lo = __half22float2(*(const half2*)&pk.x);
        float2 hi = __half22float2(*(const half2*)&pk.y);
        acc.x = fmaf(lo.x, w, acc.x);
        acc.y = fmaf(lo.y, w, acc.y);
        acc.z = fmaf(hi.x, w, acc.z);
        acc.w = fmaf(hi.y, w, acc.w);
    }
#pragma unroll
    for (int off = 16; off >= 2; off >>= 1) {
        acc.x += __shfl_down_sync(0xffffffff, acc.x, off);
        acc.y += __shfl_down_sync(0xffffffff, acc.y, off);
        acc.z += __shfl_down_sync(0xffffffff, acc.z, off);
        acc.w += __shfl_down_sync(0xffffffff, acc.w, off);
    }
    if (lane < 2) {
        // add self loop
        uint2 pk = *(const uint2*)(d_g2h + (size_t)wg * H2PAD + q * 4);
        float2 lo = __half22float2(*(const half2*)&pk.x);
        float2 hi = __half22float2(*(const half2*)&pk.y);
        acc.x += lo.x; acc.y += lo.y; acc.z += hi.x; acc.w += hi.y;
        // lane 0 collects lane 1's chunk (sub-warp, mask 0x3)
        float ox = __shfl_down_sync(0x3, acc.x, 1);
        float oy = __shfl_down_sync(0x3, acc.y, 1);
        float oz = __shfl_down_sync(0x3, acc.z, 1);
        float ow = __shfl_down_sync(0x3, acc.w, 1);
        if (lane == 0) {
            float di = d_dinv[wg];
            float v[NCLS];
            v[0] = acc.x * di + __ldg(&b2[0]);
            v[1] = acc.y * di + __ldg(&b2[1]);
            v[2] = acc.z * di + __ldg(&b2[2]);
            v[3] = acc.w * di + __ldg(&b2[3]);
            v[4] = ox    * di + __ldg(&b2[4]);
            v[5] = oy    * di + __ldg(&b2[5]);
            v[6] = oz    * di + __ldg(&b2[6]);
            float m = v[0];
#pragma unroll
            for (int c = 1; c < NCLS; c++) m = fmaxf(m, v[c]);
            float s = 0.0f;
#pragma unroll
            for (int c = 0; c < NCLS; c++) s += expf(v[c] - m);
            float lse = m + logf(s);
#pragma unroll
            for (int c = 0; c < NCLS; c++)
                out[(size_t)wg * NCLS + c] = v[c] - lse;
        }
    }
}

extern "C" void kernel_launch(void* const* d_in, const int* in_sizes, int n_in,
                              void* d_out, int out_size) {
    const float* x  = (const float*)d_in[0];
    const int*   ei = (const int*)d_in[1];
    const float* ew = (const float*)d_in[2];
    const float* W1 = (const float*)d_in[3];
    const float* b1 = (const float*)d_in[4];
    const float* W2 = (const float*)d_in[5];
    const float* b2 = (const float*)d_in[6];
    float* out = (float*)d_out;

    const int TB = 256;
    const int nodeGrid = (N_NODES + TB - 1) / TB;
    const int edgeGrid = (N_EDGES + TB - 1) / TB;
    const int warpNodeGrid = (N_NODES * 32 + TB - 1) / TB;   // warp per node

    k_zero<<<nodeGrid, TB>>>();
    k_hist<<<edgeGrid, TB>>>(ei, ew);
    k_scanA<<<NB_SCAN, 1024>>>();
    k_scanC<<<nodeGrid, TB>>>();
    k_reorder<<<edgeGrid, TB>>>(ei, ew);
    k_gemm1<<<nodeGrid, TB>>>(x, W1);
    k_agg1l2<<<warpNodeGrid, TB>>>(b1, W2);
    k_agg2out<<<warpNodeGrid, TB>>>(b2, out);
}

// round 10
// speedup vs baseline: 1.1066x; 1.0600x over previous
#include <cuda_runtime.h>
#include <cuda_fp16.h>
#include <cstdint>

#define N_NODES 100000
#define N_EDGES 3200000
#define D_FEAT  128
#define HIDDEN  16
#define NCLS    7
#define H2PAD   8
#define NB_SCAN ((N_NODES + 1023) / 1024)   // 98 scan blocks

// ---- scratch (static __device__ arrays; no allocation allowed) ----
__device__ int    d_cd  [2 * N_NODES];        // interleaved {count, deg_bits}; zero-init, reset by k_gemm1
__device__ float  d_dinv[N_NODES];
__device__ __half d_g1h [N_NODES * HIDDEN];   // fp16 messages, layer 1
__device__ float  d_acc1[N_NODES * HIDDEN];
__device__ __half d_g2h [N_NODES * H2PAD];    // fp16 messages, layer 2
__device__ float  d_acc2[N_NODES * H2PAD];
__device__ int    d_off   [N_NODES + 1];
__device__ int    d_cursor[N_NODES];
__device__ int    d_btot  [NB_SCAN];
__device__ int2   d_edge_s[N_EDGES];          // dst-sorted {src, w_as_int}

// histogram + weighted degree (d_cd starts all-zero every call)
__global__ void k_hist(const int* __restrict__ ei,
                       const float* __restrict__ ew) {
    int e = blockIdx.x * blockDim.x + threadIdx.x;
    if (e >= N_EDGES) return;
    int dst = ei[N_EDGES + e];
    atomicAdd(&d_cd[2 * dst], 1);
    atomicAdd((float*)&d_cd[2 * dst + 1], ew[e]);
}

__global__ void __launch_bounds__(1024) k_scanA() {
    __shared__ int s[1024];
    int tid = threadIdx.x;
    int i = blockIdx.x * 1024 + tid;
    int v = (i < N_NODES) ? d_cd[2 * i] : 0;
    s[tid] = v;
    __syncthreads();
#pragma unroll
    for (int off = 1; off < 1024; off <<= 1) {
        int t = (tid >= off) ? s[tid - off] : 0;
        __syncthreads();
        s[tid] += t;
        __syncthreads();
    }
    if (i < N_NODES) d_off[i] = s[tid] - v;       // exclusive within block
    if (tid == 1023) d_btot[blockIdx.x] = s[1023];
}

// scanC with the 98-element block-total scan redone per-block in smem
__global__ void __launch_bounds__(256) k_scanC() {
    __shared__ int sin[128], sscan[128];
    int t = threadIdx.x;
    if (t < 128) {
        int v = (t < NB_SCAN) ? d_btot[t] : 0;
        sin[t] = v;
        sscan[t] = v;
    }
    __syncthreads();
#pragma unroll
    for (int off = 1; off < 128; off <<= 1) {
        int tmp = (t >= off && t < 128) ? sscan[t - off] : 0;
        __syncthreads();
        if (t < 128) sscan[t] += tmp;
        __syncthreads();
    }
    int i = blockIdx.x * blockDim.x + t;
    if (i < N_NODES) {
        int k = i >> 10;
        int o = d_off[i] + (sscan[k] - sin[k]);   // + exclusive block offset
        d_off[i] = o;
        d_cursor[i] = o;
    }
    if (i == 0) d_off[N_NODES] = N_EDGES;
}

__global__ void k_reorder(const int* __restrict__ ei,
                          const float* __restrict__ ew) {
    int e = blockIdx.x * blockDim.x + threadIdx.x;
    if (e >= N_EDGES) return;
    int src = ei[e];
    int dst = ei[N_EDGES + e];
    int pos = atomicAdd(&d_cursor[dst], 1);
    d_edge_s[pos] = make_int2(src, __float_as_int(ew[e]));
}

// ---------------- layer 1 projection: g1h = half((x @ W1) * dinv) ----------------
// Also resets d_cd to zero for the next call (deterministic per-call state).
#define KCHUNK 16
__global__ void __launch_bounds__(256) k_gemm1(const float* __restrict__ x,
                                               const float* __restrict__ W1) {
    __shared__ float sW[D_FEAT * HIDDEN];
    __shared__ float sx[256][KCHUNK + 1];
    for (int i = threadIdx.x; i < D_FEAT * HIDDEN; i += blockDim.x)
        sW[i] = W1[i];

    int tid = threadIdx.x;
    int n0 = blockIdx.x * 256;
    int n  = n0 + tid;
    int nrows = min(256, N_NODES - n0);

    float acc[HIDDEN];
#pragma unroll
    for (int j = 0; j < HIDDEN; j++) acc[j] = 0.0f;

    for (int c = 0; c < D_FEAT / KCHUNK; c++) {
        __syncthreads();
        int nvec = nrows * (KCHUNK / 4);
        for (int idx = tid; idx < nvec; idx += 256) {
            int r = idx >> 2;
            int q = idx & 3;
            float4 v = *(const float4*)(x + (size_t)(n0 + r) * D_FEAT + c * KCHUNK + q * 4);
            sx[r][q * 4 + 0] = v.x;
            sx[r][q * 4 + 1] = v.y;
            sx[r][q * 4 + 2] = v.z;
            sx[r][q * 4 + 3] = v.w;
        }
        __syncthreads();
        if (n < N_NODES) {
#pragma unroll
            for (int kk = 0; kk < KCHUNK; kk++) {
                float v = sx[tid][kk];
                const float* wrow = &sW[(c * KCHUNK + kk) * HIDDEN];
#pragma unroll
                for (int j = 0; j < HIDDEN; j++)
                    acc[j] = fmaf(v, wrow[j], acc[j]);
            }
        }
    }

    if (n >= N_NODES) return;
    // deg accumulated from 0 this call; +1 self-loop here
    float di = rsqrtf(__int_as_float(d_cd[2 * n + 1]) + 1.0f);
    d_dinv[n] = di;
    // reset for next call (last reader of d_cd in the pipeline)
    *(int2*)&d_cd[2 * n] = make_int2(0, 0);
    half2* g = (half2*)(d_g1h + (size_t)n * HIDDEN);
#pragma unroll
    for (int p = 0; p < HIDDEN / 2; p++)
        g[p] = __floats2half2_rn(acc[2*p] * di, acc[2*p+1] * di);
}

// ---------------- aggregate layer 1 (warp per node, 4 lanes/edge) ----------------
__global__ void k_agg1() {
    int wg = (blockIdx.x * blockDim.x + threadIdx.x) >> 5;
    int lane = threadIdx.x & 31;
    if (wg >= N_NODES) return;
    int start = d_off[wg], end = d_off[wg + 1];
    int q = lane & 3;       // which 4-half chunk of the 16-half row
    int j = lane >> 2;      // edge slot 0..7
    float4 acc = make_float4(0.f, 0.f, 0.f, 0.f);
    for (int i = start + j; i < end; i += 8) {
        int2 ed = d_edge_s[i];
        float w = __int_as_float(ed.y);
        uint2 pk = *(const uint2*)(d_g1h + (size_t)ed.x * HIDDEN + q * 4);
        float2 lo = __half22float2(*(const half2*)&pk.x);
        float2 hi = __half22float2(*(const half2*)&pk.y);
        acc.x = fmaf(lo.x, w, acc.x);
        acc.y = fmaf(lo.y, w, acc.y);
        acc.z = fmaf(hi.x, w, acc.z);
        acc.w = fmaf(hi.y, w, acc.w);
    }
#pragma unroll
    for (int off = 16; off >= 4; off >>= 1) {
        acc.x += __shfl_down_sync(0xffffffff, acc.x, off);
        acc.y += __shfl_down_sync(0xffffffff, acc.y, off);
        acc.z += __shfl_down_sync(0xffffffff, acc.z, off);
        acc.w += __shfl_down_sync(0xffffffff, acc.w, off);
    }
    if (lane < 4) {
        uint2 pk = *(const uint2*)(d_g1h + (size_t)wg * HIDDEN + q * 4);
        float2 lo = __half22float2(*(const half2*)&pk.x);
        float2 hi = __half22float2(*(const half2*)&pk.y);
        acc.x += lo.x; acc.y += lo.y; acc.z += hi.x; acc.w += hi.y;  // self loop
        *(float4*)(d_acc1 + (size_t)wg * HIDDEN + q * 4) = acc;
    }
}

// ---------------- layer-1 epilogue + layer-2 projection ----------------
__global__ void k_layer2(const float* __restrict__ b1,
                         const float* __restrict__ W2) {
    __shared__ float sW[HIDDEN * NCLS];
    __shared__ float sb1[HIDDEN];
    if (threadIdx.x < HIDDEN * NCLS) sW[threadIdx.x] = W2[threadIdx.x];
    if (threadIdx.x < HIDDEN)        sb1[threadIdx.x] = b1[threadIdx.x];
    __syncthreads();

    int n = blockIdx.x * blockDim.x + threadIdx.x;
    if (n >= N_NODES) return;

    float di = d_dinv[n];
    float h[HIDDEN];
    const float4* a = (const float4*)(d_acc1 + (size_t)n * HIDDEN);
#pragma unroll
    for (int q = 0; q < 4; q++) {
        float4 v = a[q];
        h[q*4+0] = fmaxf(v.x * di + sb1[q*4+0], 0.0f);
        h[q*4+1] = fmaxf(v.y * di + sb1[q*4+1], 0.0f);
        h[q*4+2] = fmaxf(v.z * di + sb1[q*4+2], 0.0f);
        h[q*4+3] = fmaxf(v.w * di + sb1[q*4+3], 0.0f);
    }

    float o[H2PAD];
#pragma unroll
    for (int c = 0; c < H2PAD; c++) o[c] = 0.0f;   // o[7] stays exactly 0
#pragma unroll
    for (int j = 0; j < HIDDEN; j++) {
#pragma unroll
        for (int c = 0; c < NCLS; c++)
            o[c] = fmaf(h[j], sW[j * NCLS + c], o[c]);
    }

    half2* g = (half2*)(d_g2h + (size_t)n * H2PAD);
#pragma unroll
    for (int p = 0; p < H2PAD / 2; p++)
        g[p] = __floats2half2_rn(o[2*p] * di, o[2*p+1] * di);
}

// ---------------- aggregate layer 2 (warp per node, 2 lanes/edge) ----------------
__global__ void k_agg2() {
    int wg = (blockIdx.x * blockDim.x + threadIdx.x) >> 5;
    int lane = threadIdx.x & 31;
    if (wg >= N_NODES) return;
    int start = d_off[wg], end = d_off[wg + 1];
    int q = lane & 1;       // which 4-half chunk of the 8-half row
    int j = lane >> 1;      // edge slot 0..15
    float4 acc = make_float4(0.f, 0.f, 0.f, 0.f);
    for (int i = start + j; i < end; i += 16) {
        int2 ed = d_edge_s[i];
        float w = __int_as_float(ed.y);
        uint2 pk = *(const uint2*)(d_g2h + (size_t)ed.x * H2PAD + q * 4);
        float2 lo = __half22float2(*(const half2*)&pk.x);
        float2 hi = __half22float2(*(const half2*)&pk.y);
        acc.x = fmaf(lo.x, w, acc.x);
        acc.y = fmaf(lo.y, w, acc.y);
        acc.z = fmaf(hi.x, w, acc.z);
        acc.w = fmaf(hi.y, w, acc.w);
    }
#pragma unroll
    for (int off = 16; off >= 2; off >>= 1) {
        acc.x += __shfl_down_sync(0xffffffff, acc.x, off);
        acc.y += __shfl_down_sync(0xffffffff, acc.y, off);
        acc.z += __shfl_down_sync(0xffffffff, acc.z, off);
        acc.w += __shfl_down_sync(0xffffffff, acc.w, off);
    }
    if (lane < 2) {
        uint2 pk = *(const uint2*)(d_g2h + (size_t)wg * H2PAD + q * 4);
        float2 lo = __half22float2(*(const half2*)&pk.x);
        float2 hi = __half22float2(*(const half2*)&pk.y);
        acc.x += lo.x; acc.y += lo.y; acc.z += hi.x; acc.w += hi.y;
        *(float4*)(d_acc2 + (size_t)wg * H2PAD + q * 4) = acc;
    }
}

// ---------------- layer-2 epilogue: log_softmax ----------------
__global__ void k_out(const float* __restrict__ b2,
                      float* __restrict__ out) {
    int n = blockIdx.x * blockDim.x + threadIdx.x;
    if (n >= N_NODES) return;
    float di = d_dinv[n];
    float v[NCLS];
    const float4* a = (const float4*)(d_acc2 + (size_t)n * H2PAD);
    float4 p0 = a[0], p1 = a[1];
    v[0] = p0.x * di + b2[0];
    v[1] = p0.y * di + b2[1];
    v[2] = p0.z * di + b2[2];
    v[3] = p0.w * di + b2[3];
    v[4] = p1.x * di + b2[4];
    v[5] = p1.y * di + b2[5];
    v[6] = p1.z * di + b2[6];
    float m = v[0];
#pragma unroll
    for (int c = 1; c < NCLS; c++) m = fmaxf(m, v[c]);
    float s = 0.0f;
#pragma unroll
    for (int c = 0; c < NCLS; c++) s += expf(v[c] - m);
    float lse = m + logf(s);
#pragma unroll
    for (int c = 0; c < NCLS; c++)
        out[(size_t)n * NCLS + c] = v[c] - lse;
}

extern "C" void kernel_launch(void* const* d_in, const int* in_sizes, int n_in,
                              void* d_out, int out_size) {
    const float* x  = (const float*)d_in[0];
    const int*   ei = (const int*)d_in[1];
    const float* ew = (const float*)d_in[2];
    const float* W1 = (const float*)d_in[3];
    const float* b1 = (const float*)d_in[4];
    const float* W2 = (const float*)d_in[5];
    const float* b2 = (const float*)d_in[6];
    float* out = (float*)d_out;

    const int TB = 256;
    const int nodeGrid = (N_NODES + TB - 1) / TB;
    const int edgeGrid = (N_EDGES + TB - 1) / TB;
    const int warpNodeGrid = (N_NODES * 32 + TB - 1) / TB;   // warp per node

    k_hist<<<edgeGrid, TB>>>(ei, ew);
    k_scanA<<<NB_SCAN, 1024>>>();
    k_scanC<<<nodeGrid, TB>>>();
    k_reorder<<<edgeGrid, TB>>>(ei, ew);
    k_gemm1<<<nodeGrid, TB>>>(x, W1);
    k_agg1<<<warpNodeGrid, TB>>>();
    k_layer2<<<nodeGrid, TB>>>(b1, W2);
    k_agg2<<<warpNodeGrid, TB>>>();
    k_out<<<nodeGrid, TB>>>(b2, out);
}

// round 13
// speedup vs baseline: 1.1157x; 1.0082x over previous
#include <cuda_runtime.h>
#include <cuda_fp16.h>
#include <cstdint>

#define N_NODES 100000
#define N_EDGES 3200000
#define D_FEAT  128
#define HIDDEN  16
#define NCLS    7
#define H2PAD   8
#define NB_SCAN ((N_NODES + 1023) / 1024)   // 98 scan blocks

// ---- scratch (static __device__ arrays; no allocation allowed) ----
__device__ int    d_cd  [2 * N_NODES];        // interleaved {count, deg_bits}; zero-init, reset by k_gemm1
__device__ float  d_dinv[N_NODES];
__device__ __half d_g1h [N_NODES * HIDDEN];   // fp16 messages, layer 1
__device__ float  d_acc1[N_NODES * HIDDEN];
__device__ __half d_g2h [N_NODES * H2PAD];    // fp16 messages, layer 2
__device__ float  d_acc2[N_NODES * H2PAD];
__device__ int    d_off   [N_NODES + 1];
__device__ int    d_cursor[N_NODES];
__device__ int    d_btot  [NB_SCAN];
__device__ int2   d_edge_s[N_EDGES];          // dst-sorted {src, w_as_int}

// histogram + weighted degree, 4 edges per thread for MLP
__global__ void k_hist(const int* __restrict__ ei,
                       const float* __restrict__ ew) {
    int t = blockIdx.x * blockDim.x + threadIdx.x;
    int e = t * 4;
    if (e >= N_EDGES) return;
    int4   dst = *(const int4*)(ei + N_EDGES + e);
    float4 w   = *(const float4*)(ew + e);
    atomicAdd(&d_cd[2 * dst.x], 1);
    atomicAdd(&d_cd[2 * dst.y], 1);
    atomicAdd(&d_cd[2 * dst.z], 1);
    atomicAdd(&d_cd[2 * dst.w], 1);
    atomicAdd((float*)&d_cd[2 * dst.x + 1], w.x);
    atomicAdd((float*)&d_cd[2 * dst.y + 1], w.y);
    atomicAdd((float*)&d_cd[2 * dst.z + 1], w.z);
    atomicAdd((float*)&d_cd[2 * dst.w + 1], w.w);
}

__global__ void __launch_bounds__(1024) k_scanA() {
    __shared__ int s[1024];
    int tid = threadIdx.x;
    int i = blockIdx.x * 1024 + tid;
    int v = (i < N_NODES) ? d_cd[2 * i] : 0;
    s[tid] = v;
    __syncthreads();
#pragma unroll
    for (int off = 1; off < 1024; off <<= 1) {
        int t = (tid >= off) ? s[tid - off] : 0;
        __syncthreads();
        s[tid] += t;
        __syncthreads();
    }
    if (i < N_NODES) d_off[i] = s[tid] - v;       // exclusive within block
    if (tid == 1023) d_btot[blockIdx.x] = s[1023];
}

// scanC with the 98-element block-total scan redone per-block in smem
__global__ void __launch_bounds__(256) k_scanC() {
    __shared__ int sin[128], sscan[128];
    int t = threadIdx.x;
    if (t < 128) {
        int v = (t < NB_SCAN) ? d_btot[t] : 0;
        sin[t] = v;
        sscan[t] = v;
    }
    __syncthreads();
#pragma unroll
    for (int off = 1; off < 128; off <<= 1) {
        int tmp = (t >= off && t < 128) ? sscan[t - off] : 0;
        __syncthreads();
        if (t < 128) sscan[t] += tmp;
        __syncthreads();
    }
    int i = blockIdx.x * blockDim.x + t;
    if (i < N_NODES) {
        int k = i >> 10;
        int o = d_off[i] + (sscan[k] - sin[k]);   // + exclusive block offset
        d_off[i] = o;
        d_cursor[i] = o;
    }
    if (i == 0) d_off[N_NODES] = N_EDGES;
}

// counting-sort payload scatter, 4 edges per thread for MLP
__global__ void k_reorder(const int* __restrict__ ei,
                          const float* __restrict__ ew) {
    int t = blockIdx.x * blockDim.x + threadIdx.x;
    int e = t * 4;
    if (e >= N_EDGES) return;
    int4   src = *(const int4*)(ei + e);
    int4   dst = *(const int4*)(ei + N_EDGES + e);
    float4 w   = *(const float4*)(ew + e);
    int p0 = atomicAdd(&d_cursor[dst.x], 1);
    int p1 = atomicAdd(&d_cursor[dst.y], 1);
    int p2 = atomicAdd(&d_cursor[dst.z], 1);
    int p3 = atomicAdd(&d_cursor[dst.w], 1);
    d_edge_s[p0] = make_int2(src.x, __float_as_int(w.x));
    d_edge_s[p1] = make_int2(src.y, __float_as_int(w.y));
    d_edge_s[p2] = make_int2(src.z, __float_as_int(w.z));
    d_edge_s[p3] = make_int2(src.w, __float_as_int(w.w));
}

// ---------------- layer 1 projection: g1h = half((x @ W1) * dinv) ----------------
// Also resets d_cd to zero for the next call (deterministic per-call state).
#define KCHUNK 16
__global__ void __launch_bounds__(256) k_gemm1(const float* __restrict__ x,
                                               const float* __restrict__ W1) {
    __shared__ float sW[D_FEAT * HIDDEN];
    __shared__ float sx[256][KCHUNK + 1];
    for (int i = threadIdx.x; i < D_FEAT * HIDDEN; i += blockDim.x)
        sW[i] = W1[i];

    int tid = threadIdx.x;
    int n0 = blockIdx.x * 256;
    int n  = n0 + tid;
    int nrows = min(256, N_NODES - n0);

    float acc[HIDDEN];
#pragma unroll
    for (int j = 0; j < HIDDEN; j++) acc[j] = 0.0f;

    for (int c = 0; c < D_FEAT / KCHUNK; c++) {
        __syncthreads();
        int nvec = nrows * (KCHUNK / 4);
        for (int idx = tid; idx < nvec; idx += 256) {
            int r = idx >> 2;
            int q = idx & 3;
            float4 v = *(const float4*)(x + (size_t)(n0 + r) * D_FEAT + c * KCHUNK + q * 4);
            sx[r][q * 4 + 0] = v.x;
            sx[r][q * 4 + 1] = v.y;
            sx[r][q * 4 + 2] = v.z;
            sx[r][q * 4 + 3] = v.w;
        }
        __syncthreads();
        if (n < N_NODES) {
#pragma unroll
            for (int kk = 0; kk < KCHUNK; kk++) {
                float v = sx[tid][kk];
                const float* wrow = &sW[(c * KCHUNK + kk) * HIDDEN];
#pragma unroll
                for (int j = 0; j < HIDDEN; j++)
                    acc[j] = fmaf(v, wrow[j], acc[j]);
            }
        }
    }

    if (n >= N_NODES) return;
    // deg accumulated from 0 this call; +1 self-loop here
    float di = rsqrtf(__int_as_float(d_cd[2 * n + 1]) + 1.0f);
    d_dinv[n] = di;
    // reset for next call (last reader of d_cd in the pipeline)
    *(int2*)&d_cd[2 * n] = make_int2(0, 0);
    half2* g = (half2*)(d_g1h + (size_t)n * HIDDEN);
#pragma unroll
    for (int p = 0; p < HIDDEN / 2; p++)
        g[p] = __floats2half2_rn(acc[2*p] * di, acc[2*p+1] * di);
}

// ---------------- aggregate layer 1 (warp per node, 4 lanes/edge) ----------------
__global__ void k_agg1() {
    int wg = (blockIdx.x * blockDim.x + threadIdx.x) >> 5;
    int lane = threadIdx.x & 31;
    if (wg >= N_NODES) return;
    int start = d_off[wg], end = d_off[wg + 1];
    int q = lane & 3;       // which 4-half chunk of the 16-half row
    int j = lane >> 2;      // edge slot 0..7
    float4 acc = make_float4(0.f, 0.f, 0.f, 0.f);
    for (int i = start + j; i < end; i += 8) {
        int2 ed = d_edge_s[i];
        float w = __int_as_float(ed.y);
        uint2 pk = *(const uint2*)(d_g1h + (size_t)ed.x * HIDDEN + q * 4);
        float2 lo = __half22float2(*(const half2*)&pk.x);
        float2 hi = __half22float2(*(const half2*)&pk.y);
        acc.x = fmaf(lo.x, w, acc.x);
        acc.y = fmaf(lo.y, w, acc.y);
        acc.z = fmaf(hi.x, w, acc.z);
        acc.w = fmaf(hi.y, w, acc.w);
    }
#pragma unroll
    for (int off = 16; off >= 4; off >>= 1) {
        acc.x += __shfl_down_sync(0xffffffff, acc.x, off);
        acc.y += __shfl_down_sync(0xffffffff, acc.y, off);
        acc.z += __shfl_down_sync(0xffffffff, acc.z, off);
        acc.w += __shfl_down_sync(0xffffffff, acc.w, off);
    }
    if (lane < 4) {
        uint2 pk = *(const uint2*)(d_g1h + (size_t)wg * HIDDEN + q * 4);
        float2 lo = __half22float2(*(const half2*)&pk.x);
        float2 hi = __half22float2(*(const half2*)&pk.y);
        acc.x += lo.x; acc.y += lo.y; acc.z += hi.x; acc.w += hi.y;  // self loop
        *(float4*)(d_acc1 + (size_t)wg * HIDDEN + q * 4) = acc;
    }
}

// ---------------- layer-1 epilogue + layer-2 projection ----------------
__global__ void k_layer2(const float* __restrict__ b1,
                         const float* __restrict__ W2) {
    __shared__ float sW[HIDDEN * NCLS];
    __shared__ float sb1[HIDDEN];
    if (threadIdx.x < HIDDEN * NCLS) sW[threadIdx.x] = W2[threadIdx.x];
    if (threadIdx.x < HIDDEN)        sb1[threadIdx.x] = b1[threadIdx.x];
    __syncthreads();

    int n = blockIdx.x * blockDim.x + threadIdx.x;
    if (n >= N_NODES) return;

    float di = d_dinv[n];
    float h[HIDDEN];
    const float4* a = (const float4*)(d_acc1 + (size_t)n * HIDDEN);
#pragma unroll
    for (int q = 0; q < 4; q++) {
        float4 v = a[q];
        h[q*4+0] = fmaxf(v.x * di + sb1[q*4+0], 0.0f);
        h[q*4+1] = fmaxf(v.y * di + sb1[q*4+1], 0.0f);
        h[q*4+2] = fmaxf(v.z * di + sb1[q*4+2], 0.0f);
        h[q*4+3] = fmaxf(v.w * di + sb1[q*4+3], 0.0f);
    }

    float o[H2PAD];
#pragma unroll
    for (int c = 0; c < H2PAD; c++) o[c] = 0.0f;   // o[7] stays exactly 0
#pragma unroll
    for (int j = 0; j < HIDDEN; j++) {
#pragma unroll
        for (int c = 0; c < NCLS; c++)
            o[c] = fmaf(h[j], sW[j * NCLS + c], o[c]);
    }

    half2* g = (half2*)(d_g2h + (size_t)n * H2PAD);
#pragma unroll
    for (int p = 0; p < H2PAD / 2; p++)
        g[p] = __floats2half2_rn(o[2*p] * di, o[2*p+1] * di);
}

// ---------------- aggregate layer 2 (warp per node, 2 lanes/edge) ----------------
__global__ void k_agg2() {
    int wg = (blockIdx.x * blockDim.x + threadIdx.x) >> 5;
    int lane = threadIdx.x & 31;
    if (wg >= N_NODES) return;
    int start = d_off[wg], end = d_off[wg + 1];
    int q = lane & 1;       // which 4-half chunk of the 8-half row
    int j = lane >> 1;      // edge slot 0..15
    float4 acc = make_float4(0.f, 0.f, 0.f, 0.f);
    for (int i = start + j; i < end; i += 16) {
        int2 ed = d_edge_s[i];
        float w = __int_as_float(ed.y);
        uint2 pk = *(const uint2*)(d_g2h + (size_t)ed.x * H2PAD + q * 4);
        float2 lo = __half22float2(*(const half2*)&pk.x);
        float2 hi = __half22float2(*(const half2*)&pk.y);
        acc.x = fmaf(lo.x, w, acc.x);
        acc.y = fmaf(lo.y, w, acc.y);
        acc.z = fmaf(hi.x, w, acc.z);
        acc.w = fmaf(hi.y, w, acc.w);
    }
#pragma unroll
    for (int off = 16; off >= 2; off >>= 1) {
        acc.x += __shfl_down_sync(0xffffffff, acc.x, off);
        acc.y += __shfl_down_sync(0xffffffff, acc.y, off);
        acc.z += __shfl_down_sync(0xffffffff, acc.z, off);
        acc.w += __shfl_down_sync(0xffffffff, acc.w, off);
    }
    if (lane < 2) {
        uint2 pk = *(const uint2*)(d_g2h + (size_t)wg * H2PAD + q * 4);
        float2 lo = __half22float2(*(const half2*)&pk.x);
        float2 hi = __half22float2(*(const half2*)&pk.y);
        acc.x += lo.x; acc.y += lo.y; acc.z += hi.x; acc.w += hi.y;
        *(float4*)(d_acc2 + (size_t)wg * H2PAD + q * 4) = acc;
    }
}

// ---------------- layer-2 epilogue: log_softmax ----------------
__global__ void k_out(const float* __restrict__ b2,
                      float* __restrict__ out) {
    int n = blockIdx.x * blockDim.x + threadIdx.x;
    if (n >= N_NODES) return;
    float di = d_dinv[n];
    float v[NCLS];
    const float4* a = (const float4*)(d_acc2 + (size_t)n * H2PAD);
    float4 p0 = a[0], p1 = a[1];
    v[0] = p0.x * di + b2[0];
    v[1] = p0.y * di + b2[1];
    v[2] = p0.z * di + b2[2];
    v[3] = p0.w * di + b2[3];
    v[4] = p1.x * di + b2[4];
    v[5] = p1.y * di + b2[5];
    v[6] = p1.z * di + b2[6];
    float m = v[0];
#pragma unroll
    for (int c = 1; c < NCLS; c++) m = fmaxf(m, v[c]);
    float s = 0.0f;
#pragma unroll
    for (int c = 0; c < NCLS; c++) s += expf(v[c] - m);
    float lse = m + logf(s);
#pragma unroll
    for (int c = 0; c < NCLS; c++)
        out[(size_t)n * NCLS + c] = v[c] - lse;
}

extern "C" void kernel_launch(void* const* d_in, const int* in_sizes, int n_in,
                              void* d_out, int out_size) {
    const float* x  = (const float*)d_in[0];
    const int*   ei = (const int*)d_in[1];
    const float* ew = (const float*)d_in[2];
    const float* W1 = (const float*)d_in[3];
    const float* b1 = (const float*)d_in[4];
    const float* W2 = (const float*)d_in[5];
    const float* b2 = (const float*)d_in[6];
    float* out = (float*)d_out;

    const int TB = 256;
    const int nodeGrid  = (N_NODES + TB - 1) / TB;
    const int edge4Grid = (N_EDGES / 4 + TB - 1) / TB;       // 4 edges per thread
    const int warpNodeGrid = (N_NODES * 32 + TB - 1) / TB;   // warp per node

    k_hist<<<edge4Grid, TB>>>(ei, ew);
    k_scanA<<<NB_SCAN, 1024>>>();
    k_scanC<<<nodeGrid, TB>>>();
    k_reorder<<<edge4Grid, TB>>>(ei, ew);
    k_gemm1<<<nodeGrid, TB>>>(x, W1);
    k_agg1<<<warpNodeGrid, TB>>>();
    k_layer2<<<nodeGrid, TB>>>(b1, W2);
    k_agg2<<<warpNodeGrid, TB>>>();
    k_out<<<nodeGrid, TB>>>(b2, out);
}

// round 14
// speedup vs baseline: 1.1462x; 1.0274x over previous
#include <cuda_runtime.h>
#include <cuda_fp16.h>
#include <cstdint>

#define N_NODES 100000
#define N_EDGES 3200000
#define D_FEAT  128
#define HIDDEN  16
#define NCLS    7
#define H2PAD   8
#define NB_SCAN ((N_NODES + 1023) / 1024)   // 98 scan blocks

// ---- scratch (static __device__ arrays; no allocation allowed) ----
__device__ int    d_cd  [2 * N_NODES];        // interleaved {count, deg_bits}; zero-init, reset by k_scanC
__device__ float  d_dinv[N_NODES];
__device__ __half d_g1h [N_NODES * HIDDEN];   // fp16 messages, layer 1
__device__ float  d_acc1[N_NODES * HIDDEN];
__device__ __half d_g2h [N_NODES * H2PAD];    // fp16 messages, layer 2
__device__ float  d_acc2[N_NODES * H2PAD];
__device__ int    d_off [N_NODES + 1];
__device__ int    d_rank[N_EDGES];            // per-edge rank within its dst segment
__device__ int    d_btot[NB_SCAN];
__device__ int2   d_edge_s[N_EDGES];          // dst-sorted {src, w_as_int}

// histogram + weighted degree + per-edge rank, 4 edges per thread
__global__ void k_hist(const int* __restrict__ ei,
                       const float* __restrict__ ew) {
    int t = blockIdx.x * blockDim.x + threadIdx.x;
    int e = t * 4;
    if (e >= N_EDGES) return;
    int4   dst = *(const int4*)(ei + N_EDGES + e);
    float4 w   = *(const float4*)(ew + e);
    int4 r;
    r.x = atomicAdd(&d_cd[2 * dst.x], 1);
    r.y = atomicAdd(&d_cd[2 * dst.y], 1);
    r.z = atomicAdd(&d_cd[2 * dst.z], 1);
    r.w = atomicAdd(&d_cd[2 * dst.w], 1);
    atomicAdd((float*)&d_cd[2 * dst.x + 1], w.x);
    atomicAdd((float*)&d_cd[2 * dst.y + 1], w.y);
    atomicAdd((float*)&d_cd[2 * dst.z + 1], w.z);
    atomicAdd((float*)&d_cd[2 * dst.w + 1], w.w);
    *(int4*)(d_rank + e) = r;
}

__global__ void __launch_bounds__(1024) k_scanA() {
    __shared__ int s[1024];
    int tid = threadIdx.x;
    int i = blockIdx.x * 1024 + tid;
    int v = (i < N_NODES) ? d_cd[2 * i] : 0;
    s[tid] = v;
    __syncthreads();
#pragma unroll
    for (int off = 1; off < 1024; off <<= 1) {
        int t = (tid >= off) ? s[tid - off] : 0;
        __syncthreads();
        s[tid] += t;
        __syncthreads();
    }
    if (i < N_NODES) d_off[i] = s[tid] - v;       // exclusive within block
    if (tid == 1023) d_btot[blockIdx.x] = s[1023];
}

// scanC: finish the scan, compute dinv, reset d_cd for the next call
__global__ void __launch_bounds__(256) k_scanC() {
    __shared__ int sin[128], sscan[128];
    int t = threadIdx.x;
    if (t < 128) {
        int v = (t < NB_SCAN) ? d_btot[t] : 0;
        sin[t] = v;
        sscan[t] = v;
    }
    __syncthreads();
#pragma unroll
    for (int off = 1; off < 128; off <<= 1) {
        int tmp = (t >= off && t < 128) ? sscan[t - off] : 0;
        __syncthreads();
        if (t < 128) sscan[t] += tmp;
        __syncthreads();
    }
    int i = blockIdx.x * blockDim.x + t;
    if (i < N_NODES) {
        int k = i >> 10;
        d_off[i] += (sscan[k] - sin[k]);          // + exclusive block offset
        // dinv from accumulated degree (+1 self loop), then reset pair
        float deg = __int_as_float(d_cd[2 * i + 1]);
        d_dinv[i] = rsqrtf(deg + 1.0f);
        *(int2*)&d_cd[2 * i] = make_int2(0, 0);
    }
    if (i == 0) d_off[N_NODES] = N_EDGES;
}

// counting-sort payload scatter: NO atomic — pos = off[dst] + rank[e]
__global__ void k_reorder(const int* __restrict__ ei,
                          const float* __restrict__ ew) {
    int t = blockIdx.x * blockDim.x + threadIdx.x;
    int e = t * 4;
    if (e >= N_EDGES) return;
    int4   src = *(const int4*)(ei + e);
    int4   dst = *(const int4*)(ei + N_EDGES + e);
    float4 w   = *(const float4*)(ew + e);
    int4   r   = *(const int4*)(d_rank + e);
    d_edge_s[d_off[dst.x] + r.x] = make_int2(src.x, __float_as_int(w.x));
    d_edge_s[d_off[dst.y] + r.y] = make_int2(src.y, __float_as_int(w.y));
    d_edge_s[d_off[dst.z] + r.z] = make_int2(src.z, __float_as_int(w.z));
    d_edge_s[d_off[dst.w] + r.w] = make_int2(src.w, __float_as_int(w.w));
}

// ---------------- layer 1 projection: g1h = half((x @ W1) * dinv) ----------------
#define KCHUNK 16
__global__ void __launch_bounds__(256) k_gemm1(const float* __restrict__ x,
                                               const float* __restrict__ W1) {
    __shared__ float sW[D_FEAT * HIDDEN];
    __shared__ float sx[256][KCHUNK + 1];
    for (int i = threadIdx.x; i < D_FEAT * HIDDEN; i += blockDim.x)
        sW[i] = W1[i];

    int tid = threadIdx.x;
    int n0 = blockIdx.x * 256;
    int n  = n0 + tid;
    int nrows = min(256, N_NODES - n0);

    float acc[HIDDEN];
#pragma unroll
    for (int j = 0; j < HIDDEN; j++) acc[j] = 0.0f;

    for (int c = 0; c < D_FEAT / KCHUNK; c++) {
        __syncthreads();
        int nvec = nrows * (KCHUNK / 4);
        for (int idx = tid; idx < nvec; idx += 256) {
            int r = idx >> 2;
            int q = idx & 3;
            float4 v = *(const float4*)(x + (size_t)(n0 + r) * D_FEAT + c * KCHUNK + q * 4);
            sx[r][q * 4 + 0] = v.x;
            sx[r][q * 4 + 1] = v.y;
            sx[r][q * 4 + 2] = v.z;
            sx[r][q * 4 + 3] = v.w;
        }
        __syncthreads();
        if (n < N_NODES) {
#pragma unroll
            for (int kk = 0; kk < KCHUNK; kk++) {
                float v = sx[tid][kk];
                const float* wrow = &sW[(c * KCHUNK + kk) * HIDDEN];
#pragma unroll
                for (int j = 0; j < HIDDEN; j++)
                    acc[j] = fmaf(v, wrow[j], acc[j]);
            }
        }
    }

    if (n >= N_NODES) return;
    float di = d_dinv[n];
    half2* g = (half2*)(d_g1h + (size_t)n * HIDDEN);
#pragma unroll
    for (int p = 0; p < HIDDEN / 2; p++)
        g[p] = __floats2half2_rn(acc[2*p] * di, acc[2*p+1] * di);
}

// ---------------- aggregate layer 1 (warp per node, 4 lanes/edge) ----------------
__global__ void k_agg1() {
    int wg = (blockIdx.x * blockDim.x + threadIdx.x) >> 5;
    int lane = threadIdx.x & 31;
    if (wg >= N_NODES) return;
    int start = d_off[wg], end = d_off[wg + 1];
    int q = lane & 3;       // which 4-half chunk of the 16-half row
    int j = lane >> 2;      // edge slot 0..7
    float4 acc = make_float4(0.f, 0.f, 0.f, 0.f);
    for (int i = start + j; i < end; i += 8) {
        int2 ed = d_edge_s[i];
        float w = __int_as_float(ed.y);
        uint2 pk = *(const uint2*)(d_g1h + (size_t)ed.x * HIDDEN + q * 4);
        float2 lo = __half22float2(*(const half2*)&pk.x);
        float2 hi = __half22float2(*(const half2*)&pk.y);
        acc.x = fmaf(lo.x, w, acc.x);
        acc.y = fmaf(lo.y, w, acc.y);
        acc.z = fmaf(hi.x, w, acc.z);
        acc.w = fmaf(hi.y, w, acc.w);
    }
#pragma unroll
    for (int off = 16; off >= 4; off >>= 1) {
        acc.x += __shfl_down_sync(0xffffffff, acc.x, off);
        acc.y += __shfl_down_sync(0xffffffff, acc.y, off);
        acc.z += __shfl_down_sync(0xffffffff, acc.z, off);
        acc.w += __shfl_down_sync(0xffffffff, acc.w, off);
    }
    if (lane < 4) {
        uint2 pk = *(const uint2*)(d_g1h + (size_t)wg * HIDDEN + q * 4);
        float2 lo = __half22float2(*(const half2*)&pk.x);
        float2 hi = __half22float2(*(const half2*)&pk.y);
        acc.x += lo.x; acc.y += lo.y; acc.z += hi.x; acc.w += hi.y;  // self loop
        *(float4*)(d_acc1 + (size_t)wg * HIDDEN + q * 4) = acc;
    }
}

// ---------------- layer-1 epilogue + layer-2 projection ----------------
__global__ void k_layer2(const float* __restrict__ b1,
                         const float* __restrict__ W2) {
    __shared__ float sW[HIDDEN * NCLS];
    __shared__ float sb1[HIDDEN];
    if (threadIdx.x < HIDDEN * NCLS) sW[threadIdx.x] = W2[threadIdx.x];
    if (threadIdx.x < HIDDEN)        sb1[threadIdx.x] = b1[threadIdx.x];
    __syncthreads();

    int n = blockIdx.x * blockDim.x + threadIdx.x;
    if (n >= N_NODES) return;

    float di = d_dinv[n];
    float h[HIDDEN];
    const float4* a = (const float4*)(d_acc1 + (size_t)n * HIDDEN);
#pragma unroll
    for (int q = 0; q < 4; q++) {
        float4 v = a[q];
        h[q*4+0] = fmaxf(v.x * di + sb1[q*4+0], 0.0f);
        h[q*4+1] = fmaxf(v.y * di + sb1[q*4+1], 0.0f);
        h[q*4+2] = fmaxf(v.z * di + sb1[q*4+2], 0.0f);
        h[q*4+3] = fmaxf(v.w * di + sb1[q*4+3], 0.0f);
    }

    float o[H2PAD];
#pragma unroll
    for (int c = 0; c < H2PAD; c++) o[c] = 0.0f;   // o[7] stays exactly 0
#pragma unroll
    for (int j = 0; j < HIDDEN; j++) {
#pragma unroll
        for (int c = 0; c < NCLS; c++)
            o[c] = fmaf(h[j], sW[j * NCLS + c], o[c]);
    }

    half2* g = (half2*)(d_g2h + (size_t)n * H2PAD);
#pragma unroll
    for (int p = 0; p < H2PAD / 2; p++)
        g[p] = __floats2half2_rn(o[2*p] * di, o[2*p+1] * di);
}

// ---------------- aggregate layer 2 (warp per node, 2 lanes/edge) ----------------
__global__ void k_agg2() {
    int wg = (blockIdx.x * blockDim.x + threadIdx.x) >> 5;
    int lane = threadIdx.x & 31;
    if (wg >= N_NODES) return;
    int start = d_off[wg], end = d_off[wg + 1];
    int q = lane & 1;       // which 4-half chunk of the 8-half row
    int j = lane >> 1;      // edge slot 0..15
    float4 acc = make_float4(0.f, 0.f, 0.f, 0.f);
    for (int i = start + j; i < end; i += 16) {
        int2 ed = d_edge_s[i];
        float w = __int_as_float(ed.y);
        uint2 pk = *(const uint2*)(d_g2h + (size_t)ed.x * H2PAD + q * 4);
        float2 lo = __half22float2(*(const half2*)&pk.x);
        float2 hi = __half22float2(*(const half2*)&pk.y);
        acc.x = fmaf(lo.x, w, acc.x);
        acc.y = fmaf(lo.y, w, acc.y);
        acc.z = fmaf(hi.x, w, acc.z);
        acc.w = fmaf(hi.y, w, acc.w);
    }
#pragma unroll
    for (int off = 16; off >= 2; off >>= 1) {
        acc.x += __shfl_down_sync(0xffffffff, acc.x, off);
        acc.y += __shfl_down_sync(0xffffffff, acc.y, off);
        acc.z += __shfl_down_sync(0xffffffff, acc.z, off);
        acc.w += __shfl_down_sync(0xffffffff, acc.w, off);
    }
    if (lane < 2) {
        uint2 pk = *(const uint2*)(d_g2h + (size_t)wg * H2PAD + q * 4);
        float2 lo = __half22float2(*(const half2*)&pk.x);
        float2 hi = __half22float2(*(const half2*)&pk.y);
        acc.x += lo.x; acc.y += lo.y; acc.z += hi.x; acc.w += hi.y;
        *(float4*)(d_acc2 + (size_t)wg * H2PAD + q * 4) = acc;
    }
}

// ---------------- layer-2 epilogue: log_softmax ----------------
__global__ void k_out(const float* __restrict__ b2,
                      float* __restrict__ out) {
    int n = blockIdx.x * blockDim.x + threadIdx.x;
    if (n >= N_NODES) return;
    float di = d_dinv[n];
    float v[NCLS];
    const float4* a = (const float4*)(d_acc2 + (size_t)n * H2PAD);
    float4 p0 = a[0], p1 = a[1];
    v[0] = p0.x * di + b2[0];
    v[1] = p0.y * di + b2[1];
    v[2] = p0.z * di + b2[2];
    v[3] = p0.w * di + b2[3];
    v[4] = p1.x * di + b2[4];
    v[5] = p1.y * di + b2[5];
    v[6] = p1.z * di + b2[6];
    float m = v[0];
#pragma unroll
    for (int c = 1; c < NCLS; c++) m = fmaxf(m, v[c]);
    float s = 0.0f;
#pragma unroll
    for (int c = 0; c < NCLS; c++) s += expf(v[c] - m);
    float lse = m + logf(s);
#pragma unroll
    for (int c = 0; c < NCLS; c++)
        out[(size_t)n * NCLS + c] = v[c] - lse;
}

extern "C" void kernel_launch(void* const* d_in, const int* in_sizes, int n_in,
                              void* d_out, int out_size) {
    const float* x  = (const float*)d_in[0];
    const int*   ei = (const int*)d_in[1];
    const float* ew = (const float*)d_in[2];
    const float* W1 = (const float*)d_in[3];
    const float* b1 = (const float*)d_in[4];
    const float* W2 = (const float*)d_in[5];
    const float* b2 = (const float*)d_in[6];
    float* out = (float*)d_out;

    const int TB = 256;
    const int nodeGrid  = (N_NODES + TB - 1) / TB;
    const int edge4Grid = (N_EDGES / 4 + TB - 1) / TB;       // 4 edges per thread
    const int warpNodeGrid = (N_NODES * 32 + TB - 1) / TB;   // warp per node

    k_hist<<<edge4Grid, TB>>>(ei, ew);
    k_scanA<<<NB_SCAN, 1024>>>();
    k_scanC<<<nodeGrid, TB>>>();
    k_reorder<<<edge4Grid, TB>>>(ei, ew);
    k_gemm1<<<nodeGrid, TB>>>(x, W1);
    k_agg1<<<warpNodeGrid, TB>>>();
    k_layer2<<<nodeGrid, TB>>>(b1, W2);
    k_agg2<<<warpNodeGrid, TB>>>();
    k_out<<<nodeGrid, TB>>>(b2, out);
}

// round 15
// speedup vs baseline: 1.2250x; 1.0687x over previous
#include <cuda_runtime.h>
#include <cuda_fp16.h>
#include <cstdint>

#define N_NODES 100000
#define N_EDGES 3200000
#define D_FEAT  128
#define HIDDEN  16
#define NCLS    7
#define H2PAD   8
#define NB_SCAN ((N_NODES + 1023) / 1024)   // 98 scan blocks

// ---- scratch (static __device__ arrays; no allocation allowed) ----
__device__ int    d_cd  [2 * N_NODES];        // interleaved {count, deg_bits}; zero-init, reset by k_scanC
__device__ float  d_dinv[N_NODES];
__device__ __half d_g1h [N_NODES * HIDDEN];   // fp16 messages, layer 1
__device__ float  d_acc1[N_NODES * HIDDEN];   // gemm1 raw output, then agg1 output
__device__ __half d_g2h [N_NODES * H2PAD];    // fp16 messages, layer 2
__device__ float  d_acc2[N_NODES * H2PAD];
__device__ int    d_off [N_NODES + 1];
__device__ int    d_rank[N_EDGES];            // per-edge rank within its dst segment
__device__ int    d_btot[NB_SCAN];
__device__ int2   d_edge_s[N_EDGES];          // dst-sorted {src, w_as_int}

// histogram + weighted degree + per-edge rank, 4 edges per thread
__global__ void k_hist(const int* __restrict__ ei,
                       const float* __restrict__ ew) {
    int t = blockIdx.x * blockDim.x + threadIdx.x;
    int e = t * 4;
    if (e >= N_EDGES) return;
    int4   dst = *(const int4*)(ei + N_EDGES + e);
    float4 w   = *(const float4*)(ew + e);
    int4 r;
    r.x = atomicAdd(&d_cd[2 * dst.x], 1);
    r.y = atomicAdd(&d_cd[2 * dst.y], 1);
    r.z = atomicAdd(&d_cd[2 * dst.z], 1);
    r.w = atomicAdd(&d_cd[2 * dst.w], 1);
    atomicAdd((float*)&d_cd[2 * dst.x + 1], w.x);
    atomicAdd((float*)&d_cd[2 * dst.y + 1], w.y);
    atomicAdd((float*)&d_cd[2 * dst.z + 1], w.z);
    atomicAdd((float*)&d_cd[2 * dst.w + 1], w.w);
    *(int4*)(d_rank + e) = r;
}

__global__ void __launch_bounds__(1024) k_scanA() {
    __shared__ int s[1024];
    int tid = threadIdx.x;
    int i = blockIdx.x * 1024 + tid;
    int v = (i < N_NODES) ? d_cd[2 * i] : 0;
    s[tid] = v;
    __syncthreads();
#pragma unroll
    for (int off = 1; off < 1024; off <<= 1) {
        int t = (tid >= off) ? s[tid - off] : 0;
        __syncthreads();
        s[tid] += t;
        __syncthreads();
    }
    if (i < N_NODES) d_off[i] = s[tid] - v;       // exclusive within block
    if (tid == 1023) d_btot[blockIdx.x] = s[1023];
}

// scanC: finish the scan, compute dinv, reset d_cd for the next call
__global__ void __launch_bounds__(256) k_scanC() {
    __shared__ int sin[128], sscan[128];
    int t = threadIdx.x;
    if (t < 128) {
        int v = (t < NB_SCAN) ? d_btot[t] : 0;
        sin[t] = v;
        sscan[t] = v;
    }
    __syncthreads();
#pragma unroll
    for (int off = 1; off < 128; off <<= 1) {
        int tmp = (t >= off && t < 128) ? sscan[t - off] : 0;
        __syncthreads();
        if (t < 128) sscan[t] += tmp;
        __syncthreads();
    }
    int i = blockIdx.x * blockDim.x + t;
    if (i < N_NODES) {
        int k = i >> 10;
        d_off[i] += (sscan[k] - sin[k]);          // + exclusive block offset
        float deg = __int_as_float(d_cd[2 * i + 1]);
        d_dinv[i] = rsqrtf(deg + 1.0f);           // +1 self loop
        *(int2*)&d_cd[2 * i] = make_int2(0, 0);   // reset for next call
    }
    if (i == 0) d_off[N_NODES] = N_EDGES;
}

// counting-sort payload scatter: NO atomic — pos = off[dst] + rank[e]
__global__ void k_reorder(const int* __restrict__ ei,
                          const float* __restrict__ ew) {
    int t = blockIdx.x * blockDim.x + threadIdx.x;
    int e = t * 4;
    if (e >= N_EDGES) return;
    int4   src = *(const int4*)(ei + e);
    int4   dst = *(const int4*)(ei + N_EDGES + e);
    float4 w   = *(const float4*)(ew + e);
    int4   r   = *(const int4*)(d_rank + e);
    d_edge_s[d_off[dst.x] + r.x] = make_int2(src.x, __float_as_int(w.x));
    d_edge_s[d_off[dst.y] + r.y] = make_int2(src.y, __float_as_int(w.y));
    d_edge_s[d_off[dst.z] + r.z] = make_int2(src.z, __float_as_int(w.z));
    d_edge_s[d_off[dst.w] + r.w] = make_int2(src.w, __float_as_int(w.w));
}

// ---------------- layer 1 projection (raw, no dinv): acc1 = x @ W1 ----------------
// Runs on a second stream concurrently with the sort chain.
#define KCHUNK 16
__global__ void __launch_bounds__(256) k_gemm1raw(const float* __restrict__ x,
                                                  const float* __restrict__ W1) {
    __shared__ float sW[D_FEAT * HIDDEN];
    __shared__ float sx[256][KCHUNK + 1];
    for (int i = threadIdx.x; i < D_FEAT * HIDDEN; i += blockDim.x)
        sW[i] = W1[i];

    int tid = threadIdx.x;
    int n0 = blockIdx.x * 256;
    int n  = n0 + tid;
    int nrows = min(256, N_NODES - n0);

    float acc[HIDDEN];
#pragma unroll
    for (int j = 0; j < HIDDEN; j++) acc[j] = 0.0f;

    for (int c = 0; c < D_FEAT / KCHUNK; c++) {
        __syncthreads();
        int nvec = nrows * (KCHUNK / 4);
        for (int idx = tid; idx < nvec; idx += 256) {
            int r = idx >> 2;
            int q = idx & 3;
            float4 v = *(const float4*)(x + (size_t)(n0 + r) * D_FEAT + c * KCHUNK + q * 4);
            sx[r][q * 4 + 0] = v.x;
            sx[r][q * 4 + 1] = v.y;
            sx[r][q * 4 + 2] = v.z;
            sx[r][q * 4 + 3] = v.w;
        }
        __syncthreads();
        if (n < N_NODES) {
#pragma unroll
            for (int kk = 0; kk < KCHUNK; kk++) {
                float v = sx[tid][kk];
                const float* wrow = &sW[(c * KCHUNK + kk) * HIDDEN];
#pragma unroll
                for (int j = 0; j < HIDDEN; j++)
                    acc[j] = fmaf(v, wrow[j], acc[j]);
            }
        }
    }

    if (n >= N_NODES) return;
    float4* a = (float4*)(d_acc1 + (size_t)n * HIDDEN);
#pragma unroll
    for (int q = 0; q < 4; q++)
        a[q] = make_float4(acc[q*4+0], acc[q*4+1], acc[q*4+2], acc[q*4+3]);
}

// ---- scale raw gemm output by dinv, emit fp16 messages (join point) ----
__global__ void k_scale1() {
    int n = blockIdx.x * blockDim.x + threadIdx.x;
    if (n >= N_NODES) return;
    float di = d_dinv[n];
    const float4* a = (const float4*)(d_acc1 + (size_t)n * HIDDEN);
    half2* g = (half2*)(d_g1h + (size_t)n * HIDDEN);
#pragma unroll
    for (int q = 0; q < 4; q++) {
        float4 v = a[q];
        g[q * 2 + 0] = __floats2half2_rn(v.x * di, v.y * di);
        g[q * 2 + 1] = __floats2half2_rn(v.z * di, v.w * di);
    }
}

// ---------------- aggregate layer 1 (warp per node, 4 lanes/edge) ----------------
__global__ void k_agg1() {
    int wg = (blockIdx.x * blockDim.x + threadIdx.x) >> 5;
    int lane = threadIdx.x & 31;
    if (wg >= N_NODES) return;
    int start = d_off[wg], end = d_off[wg + 1];
    int q = lane & 3;       // which 4-half chunk of the 16-half row
    int j = lane >> 2;      // edge slot 0..7
    float4 acc = make_float4(0.f, 0.f, 0.f, 0.f);
    for (int i = start + j; i < end; i += 8) {
        int2 ed = d_edge_s[i];
        float w = __int_as_float(ed.y);
        uint2 pk = *(const uint2*)(d_g1h + (size_t)ed.x * HIDDEN + q * 4);
        float2 lo = __half22float2(*(const half2*)&pk.x);
        float2 hi = __half22float2(*(const half2*)&pk.y);
        acc.x = fmaf(lo.x, w, acc.x);
        acc.y = fmaf(lo.y, w, acc.y);
        acc.z = fmaf(hi.x, w, acc.z);
        acc.w = fmaf(hi.y, w, acc.w);
    }
#pragma unroll
    for (int off = 16; off >= 4; off >>= 1) {
        acc.x += __shfl_down_sync(0xffffffff, acc.x, off);
        acc.y += __shfl_down_sync(0xffffffff, acc.y, off);
        acc.z += __shfl_down_sync(0xffffffff, acc.z, off);
        acc.w += __shfl_down_sync(0xffffffff, acc.w, off);
    }
    if (lane < 4) {
        uint2 pk = *(const uint2*)(d_g1h + (size_t)wg * HIDDEN + q * 4);
        float2 lo = __half22float2(*(const half2*)&pk.x);
        float2 hi = __half22float2(*(const half2*)&pk.y);
        acc.x += lo.x; acc.y += lo.y; acc.z += hi.x; acc.w += hi.y;  // self loop
        *(float4*)(d_acc1 + (size_t)wg * HIDDEN + q * 4) = acc;
    }
}

// ---------------- layer-1 epilogue + layer-2 projection ----------------
__global__ void k_layer2(const float* __restrict__ b1,
                         const float* __restrict__ W2) {
    __shared__ float sW[HIDDEN * NCLS];
    __shared__ float sb1[HIDDEN];
    if (threadIdx.x < HIDDEN * NCLS) sW[threadIdx.x] = W2[threadIdx.x];
    if (threadIdx.x < HIDDEN)        sb1[threadIdx.x] = b1[threadIdx.x];
    __syncthreads();

    int n = blockIdx.x * blockDim.x + threadIdx.x;
    if (n >= N_NODES) return;

    float di = d_dinv[n];
    float h[HIDDEN];
    const float4* a = (const float4*)(d_acc1 + (size_t)n * HIDDEN);
#pragma unroll
    for (int q = 0; q < 4; q++) {
        float4 v = a[q];
        h[q*4+0] = fmaxf(v.x * di + sb1[q*4+0], 0.0f);
        h[q*4+1] = fmaxf(v.y * di + sb1[q*4+1], 0.0f);
        h[q*4+2] = fmaxf(v.z * di + sb1[q*4+2], 0.0f);
        h[q*4+3] = fmaxf(v.w * di + sb1[q*4+3], 0.0f);
    }

    float o[H2PAD];
#pragma unroll
    for (int c = 0; c < H2PAD; c++) o[c] = 0.0f;   // o[7] stays exactly 0
#pragma unroll
    for (int j = 0; j < HIDDEN; j++) {
#pragma unroll
        for (int c = 0; c < NCLS; c++)
            o[c] = fmaf(h[j], sW[j * NCLS + c], o[c]);
    }

    half2* g = (half2*)(d_g2h + (size_t)n * H2PAD);
#pragma unroll
    for (int p = 0; p < H2PAD / 2; p++)
        g[p] = __floats2half2_rn(o[2*p] * di, o[2*p+1] * di);
}

// ---------------- aggregate layer 2 (warp per node, 2 lanes/edge) ----------------
__global__ void k_agg2() {
    int wg = (blockIdx.x * blockDim.x + threadIdx.x) >> 5;
    int lane = threadIdx.x & 31;
    if (wg >= N_NODES) return;
    int start = d_off[wg], end = d_off[wg + 1];
    int q = lane & 1;       // which 4-half chunk of the 8-half row
    int j = lane >> 1;      // edge slot 0..15
    float4 acc = make_float4(0.f, 0.f, 0.f, 0.f);
    for (int i = start + j; i < end; i += 16) {
        int2 ed = d_edge_s[i];
        float w = __int_as_float(ed.y);
        uint2 pk = *(const uint2*)(d_g2h + (size_t)ed.x * H2PAD + q * 4);
        float2 lo = __half22float2(*(const half2*)&pk.x);
        float2 hi = __half22float2(*(const half2*)&pk.y);
        acc.x = fmaf(lo.x, w, acc.x);
        acc.y = fmaf(lo.y, w, acc.y);
        acc.z = fmaf(hi.x, w, acc.z);
        acc.w = fmaf(hi.y, w, acc.w);
    }
#pragma unroll
    for (int off = 16; off >= 2; off >>= 1) {
        acc.x += __shfl_down_sync(0xffffffff, acc.x, off);
        acc.y += __shfl_down_sync(0xffffffff, acc.y, off);
        acc.z += __shfl_down_sync(0xffffffff, acc.z, off);
        acc.w += __shfl_down_sync(0xffffffff, acc.w, off);
    }
    if (lane < 2) {
        uint2 pk = *(const uint2*)(d_g2h + (size_t)wg * H2PAD + q * 4);
        float2 lo = __half22float2(*(const half2*)&pk.x);
        float2 hi = __half22float2(*(const half2*)&pk.y);
        acc.x += lo.x; acc.y += lo.y; acc.z += hi.x; acc.w += hi.y;
        *(float4*)(d_acc2 + (size_t)wg * H2PAD + q * 4) = acc;
    }
}

// ---------------- layer-2 epilogue: log_softmax ----------------
__global__ void k_out(const float* __restrict__ b2,
                      float* __restrict__ out) {
    int n = blockIdx.x * blockDim.x + threadIdx.x;
    if (n >= N_NODES) return;
    float di = d_dinv[n];
    float v[NCLS];
    const float4* a = (const float4*)(d_acc2 + (size_t)n * H2PAD);
    float4 p0 = a[0], p1 = a[1];
    v[0] = p0.x * di + b2[0];
    v[1] = p0.y * di + b2[1];
    v[2] = p0.z * di + b2[2];
    v[3] = p0.w * di + b2[3];
    v[4] = p1.x * di + b2[4];
    v[5] = p1.y * di + b2[5];
    v[6] = p1.z * di + b2[6];
    float m = v[0];
#pragma unroll
    for (int c = 1; c < NCLS; c++) m = fmaxf(m, v[c]);
    float s = 0.0f;
#pragma unroll
    for (int c = 0; c < NCLS; c++) s += expf(v[c] - m);
    float lse = m + logf(s);
#pragma unroll
    for (int c = 0; c < NCLS; c++)
        out[(size_t)n * NCLS + c] = v[c] - lse;
}

extern "C" void kernel_launch(void* const* d_in, const int* in_sizes, int n_in,
                              void* d_out, int out_size) {
    const float* x  = (const float*)d_in[0];
    const int*   ei = (const int*)d_in[1];
    const float* ew = (const float*)d_in[2];
    const float* W1 = (const float*)d_in[3];
    const float* b1 = (const float*)d_in[4];
    const float* W2 = (const float*)d_in[5];
    const float* b2 = (const float*)d_in[6];
    float* out = (float*)d_out;

    // one-time resources (created on the uncaptured correctness call; the
    // captured work below is identical on every call)
    static cudaStream_t s2 = nullptr;
    static cudaEvent_t evFork = nullptr, evJoin = nullptr;
    if (s2 == nullptr) {
        cudaStreamCreateWithFlags(&s2, cudaStreamNonBlocking);
        cudaEventCreateWithFlags(&evFork, cudaEventDisableTiming);
        cudaEventCreateWithFlags(&evJoin, cudaEventDisableTiming);
    }

    const int TB = 256;
    const int nodeGrid  = (N_NODES + TB - 1) / TB;
    const int edge4Grid = (N_EDGES / 4 + TB - 1) / TB;       // 4 edges per thread
    const int warpNodeGrid = (N_NODES * 32 + TB - 1) / TB;   // warp per node

    // fork: raw GEMM on s2, sort chain on the main stream
    cudaEventRecord(evFork, 0);
    cudaStreamWaitEvent(s2, evFork, 0);
    k_gemm1raw<<<nodeGrid, TB, 0, s2>>>(x, W1);
    cudaEventRecord(evJoin, s2);

    k_hist<<<edge4Grid, TB>>>(ei, ew);
    k_scanA<<<NB_SCAN, 1024>>>();
    k_scanC<<<nodeGrid, TB>>>();
    k_reorder<<<edge4Grid, TB>>>(ei, ew);

    // join: need both gemm1raw (acc1) and scanC (dinv)
    cudaStreamWaitEvent(0, evJoin, 0);
    k_scale1<<<nodeGrid, TB>>>();
    k_agg1<<<warpNodeGrid, TB>>>();
    k_layer2<<<nodeGrid, TB>>>(b1, W2);
    k_agg2<<<warpNodeGrid, TB>>>();
    k_out<<<nodeGrid, TB>>>(b2, out);
}

// round 16
// speedup vs baseline: 1.2864x; 1.0501x over previous
#include <cuda_runtime.h>
#include <cuda_fp16.h>
#include <cstdint>

#define N_NODES 100000
#define N_EDGES 3200000
#define D_FEAT  128
#define HIDDEN  16
#define NCLS    7
#define H2PAD   8
#define NB_SCAN ((N_NODES + 1023) / 1024)   // 98 scan blocks

// ---- scratch (static __device__ arrays; no allocation allowed) ----
__device__ int      d_cd  [2 * N_NODES];      // interleaved {count, deg_bits}; zero-init, reset by k_scanC
__device__ float    d_dinv[N_NODES];
__device__ __half   d_g1h [N_NODES * HIDDEN]; // fp16 messages, layer 1
__device__ float    d_acc1[N_NODES * HIDDEN]; // gemm1 raw output, then agg1 output
__device__ __half   d_g2h [N_NODES * H2PAD];  // fp16 messages, layer 2
__device__ float    d_acc2[N_NODES * H2PAD];
__device__ int      d_off [N_NODES + 1];
__device__ int      d_rank[N_EDGES];          // per-edge rank within its dst segment
__device__ int      d_btot[NB_SCAN];
__device__ unsigned d_edge_s[N_EDGES];        // dst-sorted packed {src:17 | fp16_mag:15}

// w in [0,1) -> sign bit is 0, so 15 bits hold the full fp16 value
__device__ __forceinline__ unsigned pack_edge(int src, float w) {
    unsigned hb = __half_as_ushort(__float2half_rn(w));
    return ((unsigned)src << 15) | (hb & 0x7FFFu);
}
__device__ __forceinline__ int   edge_src(unsigned p) { return (int)(p >> 15); }
__device__ __forceinline__ float edge_w  (unsigned p) {
    return __half2float(__ushort_as_half((unsigned short)(p & 0x7FFFu)));
}

// histogram + weighted degree + per-edge rank, 4 edges per thread
__global__ void k_hist(const int* __restrict__ ei,
                       const float* __restrict__ ew) {
    int t = blockIdx.x * blockDim.x + threadIdx.x;
    int e = t * 4;
    if (e >= N_EDGES) return;
    int4   dst = *(const int4*)(ei + N_EDGES + e);
    float4 w   = *(const float4*)(ew + e);
    int4 r;
    r.x = atomicAdd(&d_cd[2 * dst.x], 1);
    r.y = atomicAdd(&d_cd[2 * dst.y], 1);
    r.z = atomicAdd(&d_cd[2 * dst.z], 1);
    r.w = atomicAdd(&d_cd[2 * dst.w], 1);
    atomicAdd((float*)&d_cd[2 * dst.x + 1], w.x);
    atomicAdd((float*)&d_cd[2 * dst.y + 1], w.y);
    atomicAdd((float*)&d_cd[2 * dst.z + 1], w.z);
    atomicAdd((float*)&d_cd[2 * dst.w + 1], w.w);
    *(int4*)(d_rank + e) = r;
}

__global__ void __launch_bounds__(1024) k_scanA() {
    __shared__ int s[1024];
    int tid = threadIdx.x;
    int i = blockIdx.x * 1024 + tid;
    int v = (i < N_NODES) ? d_cd[2 * i] : 0;
    s[tid] = v;
    __syncthreads();
#pragma unroll
    for (int off = 1; off < 1024; off <<= 1) {
        int t = (tid >= off) ? s[tid - off] : 0;
        __syncthreads();
        s[tid] += t;
        __syncthreads();
    }
    if (i < N_NODES) d_off[i] = s[tid] - v;       // exclusive within block
    if (tid == 1023) d_btot[blockIdx.x] = s[1023];
}

// scanC: finish the scan, compute dinv, reset d_cd for the next call
__global__ void __launch_bounds__(256) k_scanC() {
    __shared__ int sin[128], sscan[128];
    int t = threadIdx.x;
    if (t < 128) {
        int v = (t < NB_SCAN) ? d_btot[t] : 0;
        sin[t] = v;
        sscan[t] = v;
    }
    __syncthreads();
#pragma unroll
    for (int off = 1; off < 128; off <<= 1) {
        int tmp = (t >= off && t < 128) ? sscan[t - off] : 0;
        __syncthreads();
        if (t < 128) sscan[t] += tmp;
        __syncthreads();
    }
    int i = blockIdx.x * blockDim.x + t;
    if (i < N_NODES) {
        int k = i >> 10;
        d_off[i] += (sscan[k] - sin[k]);          // + exclusive block offset
        float deg = __int_as_float(d_cd[2 * i + 1]);
        d_dinv[i] = rsqrtf(deg + 1.0f);           // +1 self loop
        *(int2*)&d_cd[2 * i] = make_int2(0, 0);   // reset for next call
    }
    if (i == 0) d_off[N_NODES] = N_EDGES;
}

// counting-sort payload scatter: NO atomic — pos = off[dst] + rank[e]; 4B payload
__global__ void k_reorder(const int* __restrict__ ei,
                          const float* __restrict__ ew) {
    int t = blockIdx.x * blockDim.x + threadIdx.x;
    int e = t * 4;
    if (e >= N_EDGES) return;
    int4   src = *(const int4*)(ei + e);
    int4   dst = *(const int4*)(ei + N_EDGES + e);
    float4 w   = *(const float4*)(ew + e);
    int4   r   = *(const int4*)(d_rank + e);
    d_edge_s[d_off[dst.x] + r.x] = pack_edge(src.x, w.x);
    d_edge_s[d_off[dst.y] + r.y] = pack_edge(src.y, w.y);
    d_edge_s[d_off[dst.z] + r.z] = pack_edge(src.z, w.z);
    d_edge_s[d_off[dst.w] + r.w] = pack_edge(src.w, w.w);
}

// ---------------- layer 1 projection (raw, no dinv): acc1 = x @ W1 ----------------
// Runs on a second stream concurrently with the sort chain.
#define KCHUNK 16
__global__ void __launch_bounds__(256) k_gemm1raw(const float* __restrict__ x,
                                                  const float* __restrict__ W1) {
    __shared__ float sW[D_FEAT * HIDDEN];
    __shared__ float sx[256][KCHUNK + 1];
    for (int i = threadIdx.x; i < D_FEAT * HIDDEN; i += blockDim.x)
        sW[i] = W1[i];

    int tid = threadIdx.x;
    int n0 = blockIdx.x * 256;
    int n  = n0 + tid;
    int nrows = min(256, N_NODES - n0);

    float acc[HIDDEN];
#pragma unroll
    for (int j = 0; j < HIDDEN; j++) acc[j] = 0.0f;

    for (int c = 0; c < D_FEAT / KCHUNK; c++) {
        __syncthreads();
        int nvec = nrows * (KCHUNK / 4);
        for (int idx = tid; idx < nvec; idx += 256) {
            int r = idx >> 2;
            int q = idx & 3;
            float4 v = *(const float4*)(x + (size_t)(n0 + r) * D_FEAT + c * KCHUNK + q * 4);
            sx[r][q * 4 + 0] = v.x;
            sx[r][q * 4 + 1] = v.y;
            sx[r][q * 4 + 2] = v.z;
            sx[r][q * 4 + 3] = v.w;
        }
        __syncthreads();
        if (n < N_NODES) {
#pragma unroll
            for (int kk = 0; kk < KCHUNK; kk++) {
                float v = sx[tid][kk];
                const float* wrow = &sW[(c * KCHUNK + kk) * HIDDEN];
#pragma unroll
                for (int j = 0; j < HIDDEN; j++)
                    acc[j] = fmaf(v, wrow[j], acc[j]);
            }
        }
    }

    if (n >= N_NODES) return;
    float4* a = (float4*)(d_acc1 + (size_t)n * HIDDEN);
#pragma unroll
    for (int q = 0; q < 4; q++)
        a[q] = make_float4(acc[q*4+0], acc[q*4+1], acc[q*4+2], acc[q*4+3]);
}

// ---- scale raw gemm output by dinv, emit fp16 messages (join point) ----
__global__ void k_scale1() {
    int n = blockIdx.x * blockDim.x + threadIdx.x;
    if (n >= N_NODES) return;
    float di = d_dinv[n];
    const float4* a = (const float4*)(d_acc1 + (size_t)n * HIDDEN);
    half2* g = (half2*)(d_g1h + (size_t)n * HIDDEN);
#pragma unroll
    for (int q = 0; q < 4; q++) {
        float4 v = a[q];
        g[q * 2 + 0] = __floats2half2_rn(v.x * di, v.y * di);
        g[q * 2 + 1] = __floats2half2_rn(v.z * di, v.w * di);
    }
}

// ---------------- aggregate layer 1 (warp per node, 4 lanes/edge) ----------------
__global__ void k_agg1() {
    int wg = (blockIdx.x * blockDim.x + threadIdx.x) >> 5;
    int lane = threadIdx.x & 31;
    if (wg >= N_NODES) return;
    int start = d_off[wg], end = d_off[wg + 1];
    int q = lane & 3;       // which 4-half chunk of the 16-half row
    int j = lane >> 2;      // edge slot 0..7
    float4 acc = make_float4(0.f, 0.f, 0.f, 0.f);
    for (int i = start + j; i < end; i += 8) {
        unsigned p = d_edge_s[i];
        float w = edge_w(p);
        uint2 pk = *(const uint2*)(d_g1h + (size_t)edge_src(p) * HIDDEN + q * 4);
        float2 lo = __half22float2(*(const half2*)&pk.x);
        float2 hi = __half22float2(*(const half2*)&pk.y);
        acc.x = fmaf(lo.x, w, acc.x);
        acc.y = fmaf(lo.y, w, acc.y);
        acc.z = fmaf(hi.x, w, acc.z);
        acc.w = fmaf(hi.y, w, acc.w);
    }
#pragma unroll
    for (int off = 16; off >= 4; off >>= 1) {
        acc.x += __shfl_down_sync(0xffffffff, acc.x, off);
        acc.y += __shfl_down_sync(0xffffffff, acc.y, off);
        acc.z += __shfl_down_sync(0xffffffff, acc.z, off);
        acc.w += __shfl_down_sync(0xffffffff, acc.w, off);
    }
    if (lane < 4) {
        uint2 pk = *(const uint2*)(d_g1h + (size_t)wg * HIDDEN + q * 4);
        float2 lo = __half22float2(*(const half2*)&pk.x);
        float2 hi = __half22float2(*(const half2*)&pk.y);
        acc.x += lo.x; acc.y += lo.y; acc.z += hi.x; acc.w += hi.y;  // self loop
        *(float4*)(d_acc1 + (size_t)wg * HIDDEN + q * 4) = acc;
    }
}

// ---------------- layer-1 epilogue + layer-2 projection ----------------
__global__ void k_layer2(const float* __restrict__ b1,
                         const float* __restrict__ W2) {
    __shared__ float sW[HIDDEN * NCLS];
    __shared__ float sb1[HIDDEN];
    if (threadIdx.x < HIDDEN * NCLS) sW[threadIdx.x] = W2[threadIdx.x];
    if (threadIdx.x < HIDDEN)        sb1[threadIdx.x] = b1[threadIdx.x];
    __syncthreads();

    int n = blockIdx.x * blockDim.x + threadIdx.x;
    if (n >= N_NODES) return;

    float di = d_dinv[n];
    float h[HIDDEN];
    const float4* a = (const float4*)(d_acc1 + (size_t)n * HIDDEN);
#pragma unroll
    for (int q = 0; q < 4; q++) {
        float4 v = a[q];
        h[q*4+0] = fmaxf(v.x * di + sb1[q*4+0], 0.0f);
        h[q*4+1] = fmaxf(v.y * di + sb1[q*4+1], 0.0f);
        h[q*4+2] = fmaxf(v.z * di + sb1[q*4+2], 0.0f);
        h[q*4+3] = fmaxf(v.w * di + sb1[q*4+3], 0.0f);
    }

    float o[H2PAD];
#pragma unroll
    for (int c = 0; c < H2PAD; c++) o[c] = 0.0f;   // o[7] stays exactly 0
#pragma unroll
    for (int j = 0; j < HIDDEN; j++) {
#pragma unroll
        for (int c = 0; c < NCLS; c++)
            o[c] = fmaf(h[j], sW[j * NCLS + c], o[c]);
    }

    half2* g = (half2*)(d_g2h + (size_t)n * H2PAD);
#pragma unroll
    for (int p = 0; p < H2PAD / 2; p++)
        g[p] = __floats2half2_rn(o[2*p] * di, o[2*p+1] * di);
}

// ---------------- aggregate layer 2 (warp per node, 2 lanes/edge) ----------------
__global__ void k_agg2() {
    int wg = (blockIdx.x * blockDim.x + threadIdx.x) >> 5;
    int lane = threadIdx.x & 31;
    if (wg >= N_NODES) return;
    int start = d_off[wg], end = d_off[wg + 1];
    int q = lane & 1;       // which 4-half chunk of the 8-half row
    int j = lane >> 1;      // edge slot 0..15
    float4 acc = make_float4(0.f, 0.f, 0.f, 0.f);
    for (int i = start + j; i < end; i += 16) {
        unsigned p = d_edge_s[i];
        float w = edge_w(p);
        uint2 pk = *(const uint2*)(d_g2h + (size_t)edge_src(p) * H2PAD + q * 4);
        float2 lo = __half22float2(*(const half2*)&pk.x);
        float2 hi = __half22float2(*(const half2*)&pk.y);
        acc.x = fmaf(lo.x, w, acc.x);
        acc.y = fmaf(lo.y, w, acc.y);
        acc.z = fmaf(hi.x, w, acc.z);
        acc.w = fmaf(hi.y, w, acc.w);
    }
#pragma unroll
    for (int off = 16; off >= 2; off >>= 1) {
        acc.x += __shfl_down_sync(0xffffffff, acc.x, off);
        acc.y += __shfl_down_sync(0xffffffff, acc.y, off);
        acc.z += __shfl_down_sync(0xffffffff, acc.z, off);
        acc.w += __shfl_down_sync(0xffffffff, acc.w, off);
    }
    if (lane < 2) {
        uint2 pk = *(const uint2*)(d_g2h + (size_t)wg * H2PAD + q * 4);
        float2 lo = __half22float2(*(const half2*)&pk.x);
        float2 hi = __half22float2(*(const half2*)&pk.y);
        acc.x += lo.x; acc.y += lo.y; acc.z += hi.x; acc.w += hi.y;
        *(float4*)(d_acc2 + (size_t)wg * H2PAD + q * 4) = acc;
    }
}

// ---------------- layer-2 epilogue: log_softmax ----------------
__global__ void k_out(const float* __restrict__ b2,
                      float* __restrict__ out) {
    int n = blockIdx.x * blockDim.x + threadIdx.x;
    if (n >= N_NODES) return;
    float di = d_dinv[n];
    float v[NCLS];
    const float4* a = (const float4*)(d_acc2 + (size_t)n * H2PAD);
    float4 p0 = a[0], p1 = a[1];
    v[0] = p0.x * di + b2[0];
    v[1] = p0.y * di + b2[1];
    v[2] = p0.z * di + b2[2];
    v[3] = p0.w * di + b2[3];
    v[4] = p1.x * di + b2[4];
    v[5] = p1.y * di + b2[5];
    v[6] = p1.z * di + b2[6];
    float m = v[0];
#pragma unroll
    for (int c = 1; c < NCLS; c++) m = fmaxf(m, v[c]);
    float s = 0.0f;
#pragma unroll
    for (int c = 0; c < NCLS; c++) s += expf(v[c] - m);
    float lse = m + logf(s);
#pragma unroll
    for (int c = 0; c < NCLS; c++)
        out[(size_t)n * NCLS + c] = v[c] - lse;
}

extern "C" void kernel_launch(void* const* d_in, const int* in_sizes, int n_in,
                              void* d_out, int out_size) {
    const float* x  = (const float*)d_in[0];
    const int*   ei = (const int*)d_in[1];
    const float* ew = (const float*)d_in[2];
    const float* W1 = (const float*)d_in[3];
    const float* b1 = (const float*)d_in[4];
    const float* W2 = (const float*)d_in[5];
    const float* b2 = (const float*)d_in[6];
    float* out = (float*)d_out;

    // one-time resources (created on the uncaptured correctness call; the
    // captured work below is identical on every call)
    static cudaStream_t s2 = nullptr;
    static cudaEvent_t evFork = nullptr, evJoin = nullptr;
    if (s2 == nullptr) {
        cudaStreamCreateWithFlags(&s2, cudaStreamNonBlocking);
        cudaEventCreateWithFlags(&evFork, cudaEventDisableTiming);
        cudaEventCreateWithFlags(&evJoin, cudaEventDisableTiming);
    }

    const int TB = 256;
    const int nodeGrid  = (N_NODES + TB - 1) / TB;
    const int edge4Grid = (N_EDGES / 4 + TB - 1) / TB;       // 4 edges per thread
    const int warpNodeGrid = (N_NODES * 32 + TB - 1) / TB;   // warp per node

    // fork: raw GEMM on s2, sort chain on the main stream
    cudaEventRecord(evFork, 0);
    cudaStreamWaitEvent(s2, evFork, 0);
    k_gemm1raw<<<nodeGrid, TB, 0, s2>>>(x, W1);
    cudaEventRecord(evJoin, s2);

    k_hist<<<edge4Grid, TB>>>(ei, ew);
    k_scanA<<<NB_SCAN, 1024>>>();
    k_scanC<<<nodeGrid, TB>>>();
    k_reorder<<<edge4Grid, TB>>>(ei, ew);

    // join: need both gemm1raw (acc1) and scanC (dinv)
    cudaStreamWaitEvent(0, evJoin, 0);
    k_scale1<<<nodeGrid, TB>>>();
    k_agg1<<<warpNodeGrid, TB>>>();
    k_layer2<<<nodeGrid, TB>>>(b1, W2);
    k_agg2<<<warpNodeGrid, TB>>>();
    k_out<<<nodeGrid, TB>>>(b2, out);
}

// round 17
// speedup vs baseline: 1.2993x; 1.0100x over previous
#include <cuda_runtime.h>
#include <cuda_fp16.h>
#include <cstdint>

#define N_NODES 100000
#define N_EDGES 3200000
#define D_FEAT  128
#define HIDDEN  16
#define NCLS    7
#define H2PAD   8
#define NB_SCAN ((N_NODES + 1023) / 1024)   // 98 scan blocks

// ---- scratch (static __device__ arrays; no allocation allowed) ----
__device__ int      d_cd  [2 * N_NODES];      // interleaved {count, deg_bits}; zero-init, reset by k_scan
__device__ float    d_dinv[N_NODES];
__device__ __half   d_g1h [N_NODES * HIDDEN]; // fp16 messages, layer 1
__device__ float    d_acc1[N_NODES * HIDDEN]; // gemm1 raw output, then agg1 output
__device__ __half   d_g2h [N_NODES * H2PAD];  // fp16 messages, layer 2
__device__ float    d_acc2[N_NODES * H2PAD];
__device__ int      d_off [N_NODES + 1];
__device__ int      d_rank[N_EDGES];          // per-edge rank within its dst segment
__device__ unsigned d_edge_s[N_EDGES];        // dst-sorted packed {src:17 | fp16_mag:15}
// decoupled-lookback scan state (zeroed by k_hist each call)
__device__ int      d_ticket;
__device__ int      d_flag[NB_SCAN];          // 0=empty, 1=aggregate, 2=inclusive
__device__ int      d_aggr[NB_SCAN];
__device__ int      d_incl[NB_SCAN];

// w in [0,1) -> sign bit is 0, so 15 bits hold the full fp16 value
__device__ __forceinline__ unsigned pack_edge(int src, float w) {
    unsigned hb = __half_as_ushort(__float2half_rn(w));
    return ((unsigned)src << 15) | (hb & 0x7FFFu);
}
__device__ __forceinline__ int   edge_src(unsigned p) { return (int)(p >> 15); }
__device__ __forceinline__ float edge_w  (unsigned p) {
    return __half2float(__ushort_as_half((unsigned short)(p & 0x7FFFu)));
}

// histogram + weighted degree + per-edge rank, 4 edges per thread.
// Block 0 also resets the scan state for this call (scan runs strictly after).
__global__ void k_hist(const int* __restrict__ ei,
                       const float* __restrict__ ew) {
    if (blockIdx.x == 0) {
        if (threadIdx.x < NB_SCAN) d_flag[threadIdx.x] = 0;
        if (threadIdx.x == 0) d_ticket = 0;
    }
    int t = blockIdx.x * blockDim.x + threadIdx.x;
    int e = t * 4;
    if (e >= N_EDGES) return;
    int4   dst = *(const int4*)(ei + N_EDGES + e);
    float4 w   = *(const float4*)(ew + e);
    int4 r;
    r.x = atomicAdd(&d_cd[2 * dst.x], 1);
    r.y = atomicAdd(&d_cd[2 * dst.y], 1);
    r.z = atomicAdd(&d_cd[2 * dst.z], 1);
    r.w = atomicAdd(&d_cd[2 * dst.w], 1);
    atomicAdd((float*)&d_cd[2 * dst.x + 1], w.x);
    atomicAdd((float*)&d_cd[2 * dst.y + 1], w.y);
    atomicAdd((float*)&d_cd[2 * dst.z + 1], w.z);
    atomicAdd((float*)&d_cd[2 * dst.w + 1], w.w);
    *(int4*)(d_rank + e) = r;
}

// single-kernel exclusive scan (decoupled lookback) + dinv + d_cd reset
__global__ void __launch_bounds__(1024) k_scan() {
    __shared__ int s[1024];
    __shared__ int sbid;
    __shared__ int sbase;
    int tid = threadIdx.x;
    if (tid == 0) sbid = atomicAdd(&d_ticket, 1);
    __syncthreads();
    int bid = sbid;
    int i = bid * 1024 + tid;
    int v = (i < N_NODES) ? d_cd[2 * i] : 0;
    s[tid] = v;
    __syncthreads();
#pragma unroll
    for (int off = 1; off < 1024; off <<= 1) {
        int tv = (tid >= off) ? s[tid - off] : 0;
        __syncthreads();
        s[tid] += tv;
        __syncthreads();
    }
    int total = s[1023];

    if (tid < 32) {
        int lane = tid;
        if (bid == 0) {
            if (lane == 0) {
                d_incl[0] = total;
                __threadfence();
                atomicExch(&d_flag[0], 2);
                sbase = 0;
            }
        } else {
            if (lane == 0) {
                d_aggr[bid] = total;
                __threadfence();
                atomicExch(&d_flag[bid], 1);
            }
            __syncwarp();
            // warp-parallel lookback
            int sum = 0;
            int p = bid - 1;
            while (true) {
                int idx = p - lane;               // lane 0 = nearest predecessor
                int f = (idx >= 0) ? *(volatile int*)&d_flag[idx] : 2;
                while (__any_sync(0xffffffffu, f == 0)) {
                    if (idx >= 0) f = *(volatile int*)&d_flag[idx];
                }
                int val = 0;
                if (idx >= 0)
                    val = (f == 2) ? *(volatile int*)&d_incl[idx]
                                   : *(volatile int*)&d_aggr[idx];
                unsigned ball = __ballot_sync(0xffffffffu, f == 2);
                if (ball) {
                    int firstLane = __ffs(ball) - 1;   // nearest inclusive
                    int contrib = (lane <= firstLane) ? val : 0;
#pragma unroll
                    for (int o = 16; o >= 1; o >>= 1)
                        contrib += __shfl_down_sync(0xffffffffu, contrib, o);
                    contrib = __shfl_sync(0xffffffffu, contrib, 0);
                    sum += contrib;
                    break;
                } else {
#pragma unroll
                    for (int o = 16; o >= 1; o >>= 1)
                        val += __shfl_down_sync(0xffffffffu, val, o);
                    val = __shfl_sync(0xffffffffu, val, 0);
                    sum += val;
                    p -= 32;
                }
            }
            if (lane == 0) {
                d_incl[bid] = sum + total;
                __threadfence();
                atomicExch(&d_flag[bid], 2);
                sbase = sum;
            }
        }
    }
    __syncthreads();
    int base = sbase;
    if (i < N_NODES) {
        d_off[i] = base + s[tid] - v;              // exclusive scan result
        float deg = __int_as_float(d_cd[2 * i + 1]);
        d_dinv[i] = rsqrtf(deg + 1.0f);            // +1 self loop
        *(int2*)&d_cd[2 * i] = make_int2(0, 0);    // reset for next call
    }
    if (i == 0) d_off[N_NODES] = N_EDGES;
}

// counting-sort payload scatter: NO atomic — pos = off[dst] + rank[e]; 4B payload
__global__ void k_reorder(const int* __restrict__ ei,
                          const float* __restrict__ ew) {
    int t = blockIdx.x * blockDim.x + threadIdx.x;
    int e = t * 4;
    if (e >= N_EDGES) return;
    int4   src = *(const int4*)(ei + e);
    int4   dst = *(const int4*)(ei + N_EDGES + e);
    float4 w   = *(const float4*)(ew + e);
    int4   r   = *(const int4*)(d_rank + e);
    d_edge_s[d_off[dst.x] + r.x] = pack_edge(src.x, w.x);
    d_edge_s[d_off[dst.y] + r.y] = pack_edge(src.y, w.y);
    d_edge_s[d_off[dst.z] + r.z] = pack_edge(src.z, w.z);
    d_edge_s[d_off[dst.w] + r.w] = pack_edge(src.w, w.w);
}

// ---------------- layer 1 projection (raw, no dinv): acc1 = x @ W1 ----------------
// Runs on a second stream concurrently with the sort chain.
#define KCHUNK 16
__global__ void __launch_bounds__(256) k_gemm1raw(const float* __restrict__ x,
                                                  const float* __restrict__ W1) {
    __shared__ float sW[D_FEAT * HIDDEN];
    __shared__ float sx[256][KCHUNK + 1];
    for (int i = threadIdx.x; i < D_FEAT * HIDDEN; i += blockDim.x)
        sW[i] = W1[i];

    int tid = threadIdx.x;
    int n0 = blockIdx.x * 256;
    int n  = n0 + tid;
    int nrows = min(256, N_NODES - n0);

    float acc[HIDDEN];
#pragma unroll
    for (int j = 0; j < HIDDEN; j++) acc[j] = 0.0f;

    for (int c = 0; c < D_FEAT / KCHUNK; c++) {
        __syncthreads();
        int nvec = nrows * (KCHUNK / 4);
        for (int idx = tid; idx < nvec; idx += 256) {
            int r = idx >> 2;
            int q = idx & 3;
            float4 v = *(const float4*)(x + (size_t)(n0 + r) * D_FEAT + c * KCHUNK + q * 4);
            sx[r][q * 4 + 0] = v.x;
            sx[r][q * 4 + 1] = v.y;
            sx[r][q * 4 + 2] = v.z;
            sx[r][q * 4 + 3] = v.w;
        }
        __syncthreads();
        if (n < N_NODES) {
#pragma unroll
            for (int kk = 0; kk < KCHUNK; kk++) {
                float v = sx[tid][kk];
                const float* wrow = &sW[(c * KCHUNK + kk) * HIDDEN];
#pragma unroll
                for (int j = 0; j < HIDDEN; j++)
                    acc[j] = fmaf(v, wrow[j], acc[j]);
            }
        }
    }

    if (n >= N_NODES) return;
    float4* a = (float4*)(d_acc1 + (size_t)n * HIDDEN);
#pragma unroll
    for (int q = 0; q < 4; q++)
        a[q] = make_float4(acc[q*4+0], acc[q*4+1], acc[q*4+2], acc[q*4+3]);
}

// ---- scale raw gemm output by dinv, emit fp16 messages (runs on s2, overlaps reorder) ----
__global__ void k_scale1() {
    int n = blockIdx.x * blockDim.x + threadIdx.x;
    if (n >= N_NODES) return;
    float di = d_dinv[n];
    const float4* a = (const float4*)(d_acc1 + (size_t)n * HIDDEN);
    half2* g = (half2*)(d_g1h + (size_t)n * HIDDEN);
#pragma unroll
    for (int q = 0; q < 4; q++) {
        float4 v = a[q];
        g[q * 2 + 0] = __floats2half2_rn(v.x * di, v.y * di);
        g[q * 2 + 1] = __floats2half2_rn(v.z * di, v.w * di);
    }
}

// ---------------- aggregate layer 1 (warp per node, 4 lanes/edge) ----------------
__global__ void k_agg1() {
    int wg = (blockIdx.x * blockDim.x + threadIdx.x) >> 5;
    int lane = threadIdx.x & 31;
    if (wg >= N_NODES) return;
    int start = d_off[wg], end = d_off[wg + 1];
    int q = lane & 3;       // which 4-half chunk of the 16-half row
    int j = lane >> 2;      // edge slot 0..7
    float4 acc = make_float4(0.f, 0.f, 0.f, 0.f);
    for (int i = start + j; i < end; i += 8) {
        unsigned p = d_edge_s[i];
        float w = edge_w(p);
        uint2 pk = *(const uint2*)(d_g1h + (size_t)edge_src(p) * HIDDEN + q * 4);
        float2 lo = __half22float2(*(const half2*)&pk.x);
        float2 hi = __half22float2(*(const half2*)&pk.y);
        acc.x = fmaf(lo.x, w, acc.x);
        acc.y = fmaf(lo.y, w, acc.y);
        acc.z = fmaf(hi.x, w, acc.z);
        acc.w = fmaf(hi.y, w, acc.w);
    }
#pragma unroll
    for (int off = 16; off >= 4; off >>= 1) {
        acc.x += __shfl_down_sync(0xffffffff, acc.x, off);
        acc.y += __shfl_down_sync(0xffffffff, acc.y, off);
        acc.z += __shfl_down_sync(0xffffffff, acc.z, off);
        acc.w += __shfl_down_sync(0xffffffff, acc.w, off);
    }
    if (lane < 4) {
        uint2 pk = *(const uint2*)(d_g1h + (size_t)wg * HIDDEN + q * 4);
        float2 lo = __half22float2(*(const half2*)&pk.x);
        float2 hi = __half22float2(*(const half2*)&pk.y);
        acc.x += lo.x; acc.y += lo.y; acc.z += hi.x; acc.w += hi.y;  // self loop
        *(float4*)(d_acc1 + (size_t)wg * HIDDEN + q * 4) = acc;
    }
}

// ---------------- layer-1 epilogue + layer-2 projection ----------------
__global__ void k_layer2(const float* __restrict__ b1,
                         const float* __restrict__ W2) {
    __shared__ float sW[HIDDEN * NCLS];
    __shared__ float sb1[HIDDEN];
    if (threadIdx.x < HIDDEN * NCLS) sW[threadIdx.x] = W2[threadIdx.x];
    if (threadIdx.x < HIDDEN)        sb1[threadIdx.x] = b1[threadIdx.x];
    __syncthreads();

    int n = blockIdx.x * blockDim.x + threadIdx.x;
    if (n >= N_NODES) return;

    float di = d_dinv[n];
    float h[HIDDEN];
    const float4* a = (const float4*)(d_acc1 + (size_t)n * HIDDEN);
#pragma unroll
    for (int q = 0; q < 4; q++) {
        float4 v = a[q];
        h[q*4+0] = fmaxf(v.x * di + sb1[q*4+0], 0.0f);
        h[q*4+1] = fmaxf(v.y * di + sb1[q*4+1], 0.0f);
        h[q*4+2] = fmaxf(v.z * di + sb1[q*4+2], 0.0f);
        h[q*4+3] = fmaxf(v.w * di + sb1[q*4+3], 0.0f);
    }

    float o[H2PAD];
#pragma unroll
    for (int c = 0; c < H2PAD; c++) o[c] = 0.0f;   // o[7] stays exactly 0
#pragma unroll
    for (int j = 0; j < HIDDEN; j++) {
#pragma unroll
        for (int c = 0; c < NCLS; c++)
            o[c] = fmaf(h[j], sW[j * NCLS + c], o[c]);
    }

    half2* g = (half2*)(d_g2h + (size_t)n * H2PAD);
#pragma unroll
    for (int p = 0; p < H2PAD / 2; p++)
        g[p] = __floats2half2_rn(o[2*p] * di, o[2*p+1] * di);
}

// ---------------- aggregate layer 2 (warp per node, 2 lanes/edge) ----------------
__global__ void k_agg2() {
    int wg = (blockIdx.x * blockDim.x + threadIdx.x) >> 5;
    int lane = threadIdx.x & 31;
    if (wg >= N_NODES) return;
    int start = d_off[wg], end = d_off[wg + 1];
    int q = lane & 1;       // which 4-half chunk of the 8-half row
    int j = lane >> 1;      // edge slot 0..15
    float4 acc = make_float4(0.f, 0.f, 0.f, 0.f);
    for (int i = start + j; i < end; i += 16) {
        unsigned p = d_edge_s[i];
        float w = edge_w(p);
        uint2 pk = *(const uint2*)(d_g2h + (size_t)edge_src(p) * H2PAD + q * 4);
        float2 lo = __half22float2(*(const half2*)&pk.x);
        float2 hi = __half22float2(*(const half2*)&pk.y);
        acc.x = fmaf(lo.x, w, acc.x);
        acc.y = fmaf(lo.y, w, acc.y);
        acc.z = fmaf(hi.x, w, acc.z);
        acc.w = fmaf(hi.y, w, acc.w);
    }
#pragma unroll
    for (int off = 16; off >= 2; off >>= 1) {
        acc.x += __shfl_down_sync(0xffffffff, acc.x, off);
        acc.y += __shfl_down_sync(0xffffffff, acc.y, off);
        acc.z += __shfl_down_sync(0xffffffff, acc.z, off);
        acc.w += __shfl_down_sync(0xffffffff, acc.w, off);
    }
    if (lane < 2) {
        uint2 pk = *(const uint2*)(d_g2h + (size_t)wg * H2PAD + q * 4);
        float2 lo = __half22float2(*(const half2*)&pk.x);
        float2 hi = __half22float2(*(const half2*)&pk.y);
        acc.x += lo.x; acc.y += lo.y; acc.z += hi.x; acc.w += hi.y;
        *(float4*)(d_acc2 + (size_t)wg * H2PAD + q * 4) = acc;
    }
}

// ---------------- layer-2 epilogue: log_softmax ----------------
__global__ void k_out(const float* __restrict__ b2,
                      float* __restrict__ out) {
    int n = blockIdx.x * blockDim.x + threadIdx.x;
    if (n >= N_NODES) return;
    float di = d_dinv[n];
    float v[NCLS];
    const float4* a = (const float4*)(d_acc2 + (size_t)n * H2PAD);
    float4 p0 = a[0], p1 = a[1];
    v[0] = p0.x * di + b2[0];
    v[1] = p0.y * di + b2[1];
    v[2] = p0.z * di + b2[2];
    v[3] = p0.w * di + b2[3];
    v[4] = p1.x * di + b2[4];
    v[5] = p1.y * di + b2[5];
    v[6] = p1.z * di + b2[6];
    float m = v[0];
#pragma unroll
    for (int c = 1; c < NCLS; c++) m = fmaxf(m, v[c]);
    float s = 0.0f;
#pragma unroll
    for (int c = 0; c < NCLS; c++) s += expf(v[c] - m);
    float lse = m + logf(s);
#pragma unroll
    for (int c = 0; c < NCLS; c++)
        out[(size_t)n * NCLS + c] = v[c] - lse;
}

extern "C" void kernel_launch(void* const* d_in, const int* in_sizes, int n_in,
                              void* d_out, int out_size) {
    const float* x  = (const float*)d_in[0];
    const int*   ei = (const int*)d_in[1];
    const float* ew = (const float*)d_in[2];
    const float* W1 = (const float*)d_in[3];
    const float* b1 = (const float*)d_in[4];
    const float* W2 = (const float*)d_in[5];
    const float* b2 = (const float*)d_in[6];
    float* out = (float*)d_out;

    // one-time resources (created on the uncaptured correctness call; the
    // captured work below is identical on every call)
    static cudaStream_t s2 = nullptr;
    static cudaEvent_t evFork = nullptr, evScan = nullptr, evJoin = nullptr;
    if (s2 == nullptr) {
        cudaStreamCreateWithFlags(&s2, cudaStreamNonBlocking);
        cudaEventCreateWithFlags(&evFork, cudaEventDisableTiming);
        cudaEventCreateWithFlags(&evScan, cudaEventDisableTiming);
        cudaEventCreateWithFlags(&evJoin, cudaEventDisableTiming);
    }

    const int TB = 256;
    const int nodeGrid  = (N_NODES + TB - 1) / TB;
    const int edge4Grid = (N_EDGES / 4 + TB - 1) / TB;       // 4 edges per thread
    const int warpNodeGrid = (N_NODES * 32 + TB - 1) / TB;   // warp per node

    // fork: raw GEMM on s2, sort chain on the main stream
    cudaEventRecord(evFork, 0);
    cudaStreamWaitEvent(s2, evFork, 0);
    k_gemm1raw<<<nodeGrid, TB, 0, s2>>>(x, W1);

    k_hist<<<edge4Grid, TB>>>(ei, ew);
    k_scan<<<NB_SCAN, 1024>>>();
    cudaEventRecord(evScan, 0);

    // s2: scale1 needs gemm1raw (s2-ordered) + dinv (evScan); overlaps reorder
    cudaStreamWaitEvent(s2, evScan, 0);
    k_scale1<<<nodeGrid, TB, 0, s2>>>();
    cudaEventRecord(evJoin, s2);

    k_reorder<<<edge4Grid, TB>>>(ei, ew);

    // join: agg1 needs sorted edges (main) + g1h messages (s2)
    cudaStreamWaitEvent(0, evJoin, 0);
    k_agg1<<<warpNodeGrid, TB>>>();
    k_layer2<<<nodeGrid, TB>>>(b1, W2);
    k_agg2<<<warpNodeGrid, TB>>>();
    k_out<<<nodeGrid, TB>>>(b2, out);
}